// round 2
// baseline (speedup 1.0000x reference)
#include <cuda_runtime.h>
#include <math.h>

// Problem dims (fixed by the dataset)
#define BB   16
#define CC   392
#define HWP  4096          // 64*64 pixels
#define NH   8
#define HD   49            // head dim
#define HID  1568          // 4*C
#define C3   1176          // 3*C

// ---------------- scratch (static device, no allocs) ----------------
__device__ float g_h   [(size_t)BB * CC  * HWP];   // LN output (reused for LN2)
__device__ float g_qkv [(size_t)BB * C3  * HWP];
__device__ float g_attn[(size_t)BB * CC  * HWP];   // scrambled attn*v
__device__ float g_x2  [(size_t)BB * CC  * HWP];   // after proj residual
__device__ float g_mlp [(size_t)BB * HID * HWP];

// ---------------- channel LayerNorm over C per pixel ----------------
// Thread per pixel; channel loop is coalesced across threads (adjacent p).
__global__ void __launch_bounds__(256) ln_kernel(
    const float* __restrict__ x, const float* __restrict__ gma,
    const float* __restrict__ bta, float* __restrict__ out)
{
    int idx = blockIdx.x * blockDim.x + threadIdx.x;   // 0 .. B*HW-1
    int b = idx / HWP;
    int p = idx - b * HWP;
    const float* xb = x + (size_t)b * CC * HWP + p;
    float s = 0.f, s2 = 0.f;
    #pragma unroll 8
    for (int c = 0; c < CC; c++) {
        float v = xb[(size_t)c * HWP];
        s += v; s2 += v * v;
    }
    float mu  = s * (1.0f / CC);
    float var = s2 * (1.0f / CC) - mu * mu;
    float inv = rsqrtf(var + 1e-5f);
    float* ob = out + (size_t)b * CC * HWP + p;
    #pragma unroll 8
    for (int c = 0; c < CC; c++) {
        ob[(size_t)c * HWP] = (xb[(size_t)c * HWP] - mu) * inv * gma[c] + bta[c];
    }
}

// ---------------- tiled SGEMM: out[b][o][p] = sum_c W[o][c]*X[b][c][p] (+epi) --
// 128x128 tile, K-tile 8, 256 threads, 8x8 per thread in 2x2 blocks of 4x4.
// MODE: 0 = +bias (qkv)
//       1 = +bias +res (proj residual)
//       2 = +bias, exact GELU (fc1)
//       3 = +bias +res (fc2 -> final out)
template<int MODE>
__global__ void __launch_bounds__(256) gemm128(
    const float* __restrict__ Wt, const float* __restrict__ X,
    const float* __restrict__ bias, const float* __restrict__ res,
    float* __restrict__ out, int O, int K)
{
    __shared__ float As[8][128];
    __shared__ float Bs[8][128];

    int b = blockIdx.z;
    const float* Xb = X + (size_t)b * K * HWP;
    float*       Ob = out + (size_t)b * O * HWP;
    const float* Rb = res ? res + (size_t)b * O * HWP : nullptr;

    int m0 = blockIdx.y * 128;
    int n0 = blockIdx.x * 128;
    int tid = threadIdx.x;
    int tx = tid & 15;          // 0..15
    int ty = tid >> 4;          // 0..15

    // load maps
    int a_row = tid >> 1;            // 0..127  (m within tile)
    int a_col = (tid & 1) * 4;       // 0 or 4  (k offset)
    int b_row = tid >> 5;            // 0..7    (k)
    int b_col = (tid & 31) * 4;      // 0..124  (n offset)

    float acc[8][8];
    #pragma unroll
    for (int i = 0; i < 8; i++)
        #pragma unroll
        for (int j = 0; j < 8; j++) acc[i][j] = 0.f;

    for (int k0 = 0; k0 < K; k0 += 8) {
        float4 av = make_float4(0.f, 0.f, 0.f, 0.f);
        if (m0 + a_row < O)
            av = *reinterpret_cast<const float4*>(
                     &Wt[(size_t)(m0 + a_row) * K + k0 + a_col]);
        As[a_col + 0][a_row] = av.x;
        As[a_col + 1][a_row] = av.y;
        As[a_col + 2][a_row] = av.z;
        As[a_col + 3][a_row] = av.w;

        float4 bv = *reinterpret_cast<const float4*>(
                        &Xb[(size_t)(k0 + b_row) * HWP + n0 + b_col]);
        *reinterpret_cast<float4*>(&Bs[b_row][b_col]) = bv;
        __syncthreads();

        #pragma unroll
        for (int k = 0; k < 8; k++) {
            float4 a0 = *reinterpret_cast<const float4*>(&As[k][ty * 4]);
            float4 a1 = *reinterpret_cast<const float4*>(&As[k][64 + ty * 4]);
            float4 bb0 = *reinterpret_cast<const float4*>(&Bs[k][tx * 4]);
            float4 bb1 = *reinterpret_cast<const float4*>(&Bs[k][64 + tx * 4]);
            float a[8] = {a0.x, a0.y, a0.z, a0.w, a1.x, a1.y, a1.z, a1.w};
            float bbv[8] = {bb0.x, bb0.y, bb0.z, bb0.w, bb1.x, bb1.y, bb1.z, bb1.w};
            #pragma unroll
            for (int i = 0; i < 8; i++)
                #pragma unroll
                for (int j = 0; j < 8; j++)
                    acc[i][j] = fmaf(a[i], bbv[j], acc[i][j]);
        }
        __syncthreads();
    }

    // epilogue
    #pragma unroll
    for (int i = 0; i < 8; i++) {
        int mi = (i < 4) ? (ty * 4 + i) : (64 + ty * 4 + (i - 4));
        int m = m0 + mi;
        if (m >= O) continue;
        float bvv = bias[m];
        #pragma unroll
        for (int j = 0; j < 8; j++) {
            int nj = (j < 4) ? (tx * 4 + j) : (64 + tx * 4 + (j - 4));
            int nn = n0 + nj;
            float v = acc[i][j] + bvv;
            if (MODE == 1 || MODE == 3) v += Rb[(size_t)m * HWP + nn];
            if (MODE == 2) v = 0.5f * v * (1.0f + erff(v * 0.70710678118654752f));
            Ob[(size_t)m * HWP + nn] = v;
        }
    }
}

// ---------------- elementwise attention + softmax over hd ----------------
// Thread per (b, head, p). Writes the row-major-view scramble:
// out_flat[b][ head*HW*hd + p*hd + d ].
__global__ void __launch_bounds__(256) attn_kernel(
    const float* __restrict__ qkv, const float* __restrict__ rel_bias,
    float* __restrict__ out)
{
    int gid = blockIdx.x * blockDim.x + threadIdx.x;   // 0 .. B*NH*HW-1
    int p  = gid & (HWP - 1);
    int bh = gid / HWP;
    int head = bh & (NH - 1);
    int b = bh / NH;

    const float* base = qkv + (size_t)b * C3 * HWP;
    const float* qp = base + (size_t)(head * HD) * HWP + p;
    const float* kp = base + (size_t)(CC + head * HD) * HWP + p;
    const float* vp = base + (size_t)(2 * CC + head * HD) * HWP + p;
    const float scale = 0.14285714285714285f;   // 49^-0.5

    float s[HD];
    float mx = -INFINITY;
    #pragma unroll
    for (int d = 0; d < HD; d++) {
        float sv = qp[(size_t)d * HWP] * scale * kp[(size_t)d * HWP]
                   + rel_bias[head * HD + d];
        s[d] = sv;
        mx = fmaxf(mx, sv);
    }
    float sum = 0.f;
    #pragma unroll
    for (int d = 0; d < HD; d++) {
        float e = expf(s[d] - mx);
        s[d] = e;
        sum += e;
    }
    float inv = 1.0f / sum;
    float* ob = out + (size_t)b * CC * HWP
                    + (size_t)head * HWP * HD + (size_t)p * HD;
    #pragma unroll
    for (int d = 0; d < HD; d++) {
        ob[d] = s[d] * inv * vp[(size_t)d * HWP];
    }
}

// ---------------- launch ----------------
extern "C" void kernel_launch(void* const* d_in, const int* in_sizes, int n_in,
                              void* d_out, int out_size)
{
    const float* x      = (const float*)d_in[0];
    const float* ln1_g  = (const float*)d_in[1];
    const float* ln1_b  = (const float*)d_in[2];
    const float* qkv_w  = (const float*)d_in[3];
    const float* qkv_b  = (const float*)d_in[4];
    const float* relb   = (const float*)d_in[5];
    const float* proj_w = (const float*)d_in[6];
    const float* proj_b = (const float*)d_in[7];
    const float* ln2_g  = (const float*)d_in[8];
    const float* ln2_b  = (const float*)d_in[9];
    const float* fc1_w  = (const float*)d_in[10];
    const float* fc1_b  = (const float*)d_in[11];
    const float* fc2_w  = (const float*)d_in[12];
    const float* fc2_b  = (const float*)d_in[13];
    float* outp = (float*)d_out;

    float *h, *qkv, *attn, *x2, *mlp;
    cudaGetSymbolAddress((void**)&h,    g_h);
    cudaGetSymbolAddress((void**)&qkv,  g_qkv);
    cudaGetSymbolAddress((void**)&attn, g_attn);
    cudaGetSymbolAddress((void**)&x2,   g_x2);
    cudaGetSymbolAddress((void**)&mlp,  g_mlp);

    const int NPIX = BB * HWP;

    // 1) LN1: x -> h
    ln_kernel<<<NPIX / 256, 256>>>(x, ln1_g, ln1_b, h);

    // 2) qkv GEMM: [1176 x 392] @ h -> qkv
    {
        dim3 grid(HWP / 128, (C3 + 127) / 128, BB);
        gemm128<0><<<grid, 256>>>(qkv_w, h, qkv_b, nullptr, qkv, C3, CC);
    }

    // 3) elementwise attention + softmax (scrambled layout) -> attn
    attn_kernel<<<(BB * NH * HWP) / 256, 256>>>(qkv, relb, attn);

    // 4) proj GEMM + bias + shortcut(x) -> x2
    {
        dim3 grid(HWP / 128, (CC + 127) / 128, BB);
        gemm128<1><<<grid, 256>>>(proj_w, attn, proj_b, x, x2, CC, CC);
    }

    // 5) LN2: x2 -> h (reuse)
    ln_kernel<<<NPIX / 256, 256>>>(x2, ln2_g, ln2_b, h);

    // 6) fc1 GEMM + GELU -> mlp
    {
        dim3 grid(HWP / 128, (HID + 127) / 128, BB);
        gemm128<2><<<grid, 256>>>(fc1_w, h, fc1_b, nullptr, mlp, HID, CC);
    }

    // 7) fc2 GEMM + bias + residual(x2) -> out
    {
        dim3 grid(HWP / 128, (CC + 127) / 128, BB);
        gemm128<3><<<grid, 256>>>(fc2_w, mlp, fc2_b, x2, outp, CC, HID);
    }
}

// round 5
// speedup vs baseline: 2.7372x; 2.7372x over previous
#include <cuda_runtime.h>
#include <math.h>
#include <stdint.h>

// Problem dims (fixed by the dataset)
#define BB   16
#define CC   392
#define HWP  4096          // 64*64 pixels
#define NH   8
#define HD   49            // head dim
#define HID  1568          // 4*C
#define C3   1176          // 3*C

// ---------------- scratch (static device, no allocs) ----------------
__device__ float g_h   [(size_t)BB * CC  * HWP];
__device__ float g_qkv [(size_t)BB * C3  * HWP];
__device__ float g_attn[(size_t)BB * CC  * HWP];
__device__ float g_x2  [(size_t)BB * CC  * HWP];
__device__ float g_mlp [(size_t)BB * HID * HWP];

// ================= helpers =================
__device__ __forceinline__ uint32_t smem_u32(const void* p) {
    uint32_t a;
    asm("{ .reg .u64 t; cvta.to.shared.u64 t, %1; cvt.u32.u64 %0, t; }"
        : "=r"(a) : "l"(p));
    return a;
}
__device__ __forceinline__ void cp16(uint32_t saddr, const float* g, bool valid) {
    unsigned long long ga;
    asm("cvta.to.global.u64 %0, %1;" : "=l"(ga) : "l"(g));
    int sz = valid ? 16 : 0;
    asm volatile("cp.async.cg.shared.global [%0], [%1], 16, %2;"
                 :: "r"(saddr), "l"(ga), "r"(sz));
}
#define CP_COMMIT() asm volatile("cp.async.commit_group;" ::: "memory")
#define CP_WAIT2()  asm volatile("cp.async.wait_group 2;" ::: "memory")

__device__ __forceinline__ uint32_t f2tf32(float f) {
    uint32_t u;
    asm("cvt.rna.tf32.f32 %0, %1;" : "=r"(u) : "f"(f));
    return u;
}
__device__ __forceinline__ void mma_tf32(float* d, const uint32_t* a, const uint32_t* b) {
    asm volatile(
        "mma.sync.aligned.m16n8k8.row.col.f32.tf32.tf32.f32 "
        "{%0,%1,%2,%3}, {%4,%5,%6,%7}, {%8,%9}, {%0,%1,%2,%3};"
        : "+f"(d[0]), "+f"(d[1]), "+f"(d[2]), "+f"(d[3])
        : "r"(a[0]), "r"(a[1]), "r"(a[2]), "r"(a[3]), "r"(b[0]), "r"(b[1]));
}

// ================= HMMA tf32 GEMM =================
// D[o, p] = sum_k W[o][k] * X[k][p].  M = 128 out-channels, N = 128 pixels.
// A smem: [128 o][36 f] (32 k + 4 pad)   = 18432 B
// B smem: [32 k][136 f] (128 p + 8 pad)  = 17408 B
// 3 stages, stage stride 35840 B (8960 floats).
#define KT        32
#define STAGES    3
#define A_STRIDE  36
#define B_STRIDE  136
#define A_FLOATS  4608            // 128*36
#define STAGE_F   8960            // floats per stage
#define STAGE_B   35840           // bytes per stage
#define SMEM_BYTES (STAGES * STAGE_B)

template<int MODE>   // 0:+bias  1:+bias+res  2:+bias+GELU  3:+bias+res
__global__ void __launch_bounds__(256, 2)
hgemm(const float* __restrict__ Wt, const float* __restrict__ X,
      const float* __restrict__ bias, const float* __restrict__ res,
      float* __restrict__ out, int O, int K)
{
    extern __shared__ float smf[];
    const uint32_t sb = smem_u32(smf);
    const int tid  = threadIdx.x;
    const int wid  = tid >> 5;
    const int lane = tid & 31;
    const int r = lane >> 2;          // 0..7
    const int c = lane & 3;           // 0..3
    const int warp_m = (wid >> 2) * 64;   // 0 / 64
    const int warp_n = (wid & 3) * 32;    // 0..96

    const int b  = blockIdx.z;
    const int n0 = blockIdx.x * 128;      // pixel tile
    const int m0 = blockIdx.y * 128;      // out-channel tile
    const float* Xb = X + (size_t)b * K * HWP;
    float*       Ob = out + (size_t)b * O * HWP;
    const float* Rb = (MODE == 1 || MODE == 3) ? res + (size_t)b * O * HWP : nullptr;

    const int NC = (K + KT - 1) / KT;

    // ---- stage loader (pure cp.async copies) ----
    auto load_stage = [&](int stage, int k0) {
        uint32_t a_base = sb + stage * STAGE_B;
        uint32_t b_base = a_base + 18432;
        #pragma unroll
        for (int i = 0; i < 4; ++i) {               // A: 128 x 32 fl = 1024 x 16B
            int slot = tid + i * 256;
            int row = slot >> 3, kc = slot & 7;
            int o = m0 + row, k = k0 + kc * 4;
            bool v = (o < O) && (k < K);
            cp16(a_base + row * (A_STRIDE * 4) + kc * 16,
                 v ? (Wt + (size_t)o * K + k) : Wt, v);
        }
        #pragma unroll
        for (int i = 0; i < 4; ++i) {               // B: 32 x 128 fl = 1024 x 16B
            int slot = tid + i * 256;
            int kr = slot >> 5, pc = slot & 31;
            int k = k0 + kr;
            bool v = (k < K);
            cp16(b_base + kr * (B_STRIDE * 4) + pc * 16,
                 v ? (Xb + (size_t)k * HWP + n0 + pc * 4) : Xb, v);
        }
    };

    float acc[4][4][4];
    #pragma unroll
    for (int i = 0; i < 4; ++i)
        #pragma unroll
        for (int j = 0; j < 4; ++j)
            #pragma unroll
            for (int t = 0; t < 4; ++t) acc[i][j][t] = 0.f;

    // prologue: stages 0,1
    load_stage(0, 0);           CP_COMMIT();
    if (NC > 1) load_stage(1, KT);
    CP_COMMIT();

    for (int ch = 0; ch < NC; ++ch) {
        int ld = ch + STAGES - 1;
        if (ld < NC) load_stage(ld % STAGES, ld * KT);
        CP_COMMIT();
        CP_WAIT2();
        __syncthreads();

        const float* As = smf + (ch % STAGES) * STAGE_F;
        const float* Bs = As + A_FLOATS;

        #pragma unroll
        for (int kk = 0; kk < KT; kk += 8) {
            uint32_t af[4][4];
            #pragma unroll
            for (int mt = 0; mt < 4; ++mt) {
                int row = warp_m + mt * 16 + r;
                const float* ap = As + row * A_STRIDE + kk + c;
                af[mt][0] = f2tf32(ap[0]);
                af[mt][1] = f2tf32(ap[8 * A_STRIDE]);
                af[mt][2] = f2tf32(ap[4]);
                af[mt][3] = f2tf32(ap[8 * A_STRIDE + 4]);
            }
            uint32_t bf[4][2];
            #pragma unroll
            for (int nt = 0; nt < 4; ++nt) {
                int col = warp_n + nt * 8 + r;
                const float* bp = Bs + (kk + c) * B_STRIDE + col;
                bf[nt][0] = f2tf32(bp[0]);
                bf[nt][1] = f2tf32(bp[4 * B_STRIDE]);
            }
            #pragma unroll
            for (int mt = 0; mt < 4; ++mt)
                #pragma unroll
                for (int nt = 0; nt < 4; ++nt)
                    mma_tf32(acc[mt][nt], af[mt], bf[nt]);
        }
        __syncthreads();
    }

    // ---- epilogue: registers -> gmem (float2, consecutive pixels) ----
    #pragma unroll
    for (int mt = 0; mt < 4; ++mt) {
        #pragma unroll
        for (int half = 0; half < 2; ++half) {
            int o = m0 + warp_m + mt * 16 + half * 8 + r;
            if (o >= O) continue;
            float bv = bias[o];
            #pragma unroll
            for (int nt = 0; nt < 4; ++nt) {
                int p = n0 + warp_n + nt * 8 + c * 2;
                float v0 = acc[mt][nt][half * 2 + 0] + bv;
                float v1 = acc[mt][nt][half * 2 + 1] + bv;
                if (MODE == 1 || MODE == 3) {
                    float2 rv = *reinterpret_cast<const float2*>(
                                    Rb + (size_t)o * HWP + p);
                    v0 += rv.x; v1 += rv.y;
                }
                if (MODE == 2) {
                    v0 = 0.5f * v0 * (1.0f + erff(v0 * 0.70710678118654752f));
                    v1 = 0.5f * v1 * (1.0f + erff(v1 * 0.70710678118654752f));
                }
                *reinterpret_cast<float2*>(Ob + (size_t)o * HWP + p)
                    = make_float2(v0, v1);
            }
        }
    }
}

// ---------------- channel LayerNorm over C per pixel ----------------
__global__ void __launch_bounds__(256) ln_kernel(
    const float* __restrict__ x, const float* __restrict__ gma,
    const float* __restrict__ bta, float* __restrict__ out)
{
    int idx = blockIdx.x * blockDim.x + threadIdx.x;
    int b = idx / HWP;
    int p = idx - b * HWP;
    const float* xb = x + (size_t)b * CC * HWP + p;
    float s = 0.f, s2 = 0.f;
    #pragma unroll 8
    for (int c = 0; c < CC; c++) {
        float v = xb[(size_t)c * HWP];
        s += v; s2 += v * v;
    }
    float mu  = s * (1.0f / CC);
    float var = s2 * (1.0f / CC) - mu * mu;
    float inv = rsqrtf(var + 1e-5f);
    float* ob = out + (size_t)b * CC * HWP + p;
    #pragma unroll 8
    for (int c = 0; c < CC; c++) {
        ob[(size_t)c * HWP] = (xb[(size_t)c * HWP] - mu) * inv * gma[c] + bta[c];
    }
}

// ---------------- elementwise attention + softmax over hd ----------------
__global__ void __launch_bounds__(256) attn_kernel(
    const float* __restrict__ qkv, const float* __restrict__ rel_bias,
    float* __restrict__ out)
{
    int gid = blockIdx.x * blockDim.x + threadIdx.x;
    int p  = gid & (HWP - 1);
    int bh = gid / HWP;
    int head = bh & (NH - 1);
    int b = bh / NH;

    const float* base = qkv + (size_t)b * C3 * HWP;
    const float* qp = base + (size_t)(head * HD) * HWP + p;
    const float* kp = base + (size_t)(CC + head * HD) * HWP + p;
    const float* vp = base + (size_t)(2 * CC + head * HD) * HWP + p;
    const float scale = 0.14285714285714285f;   // 49^-0.5

    float s[HD];
    float mx = -INFINITY;
    #pragma unroll
    for (int d = 0; d < HD; d++) {
        float sv = qp[(size_t)d * HWP] * scale * kp[(size_t)d * HWP]
                   + rel_bias[head * HD + d];
        s[d] = sv;
        mx = fmaxf(mx, sv);
    }
    float sum = 0.f;
    #pragma unroll
    for (int d = 0; d < HD; d++) {
        float e = expf(s[d] - mx);
        s[d] = e;
        sum += e;
    }
    float inv = 1.0f / sum;
    float* ob = out + (size_t)b * CC * HWP
                    + (size_t)head * HWP * HD + (size_t)p * HD;
    #pragma unroll
    for (int d = 0; d < HD; d++) {
        ob[d] = s[d] * inv * vp[(size_t)d * HWP];
    }
}

// ---------------- launch ----------------
extern "C" void kernel_launch(void* const* d_in, const int* in_sizes, int n_in,
                              void* d_out, int out_size)
{
    const float* x      = (const float*)d_in[0];
    const float* ln1_g  = (const float*)d_in[1];
    const float* ln1_b  = (const float*)d_in[2];
    const float* qkv_w  = (const float*)d_in[3];
    const float* qkv_b  = (const float*)d_in[4];
    const float* relb   = (const float*)d_in[5];
    const float* proj_w = (const float*)d_in[6];
    const float* proj_b = (const float*)d_in[7];
    const float* ln2_g  = (const float*)d_in[8];
    const float* ln2_b  = (const float*)d_in[9];
    const float* fc1_w  = (const float*)d_in[10];
    const float* fc1_b  = (const float*)d_in[11];
    const float* fc2_w  = (const float*)d_in[12];
    const float* fc2_b  = (const float*)d_in[13];
    float* outp = (float*)d_out;

    float *h, *qkv, *attn, *x2, *mlp;
    cudaGetSymbolAddress((void**)&h,    g_h);
    cudaGetSymbolAddress((void**)&qkv,  g_qkv);
    cudaGetSymbolAddress((void**)&attn, g_attn);
    cudaGetSymbolAddress((void**)&x2,   g_x2);
    cudaGetSymbolAddress((void**)&mlp,  g_mlp);

    cudaFuncSetAttribute(hgemm<0>, cudaFuncAttributeMaxDynamicSharedMemorySize, SMEM_BYTES);
    cudaFuncSetAttribute(hgemm<1>, cudaFuncAttributeMaxDynamicSharedMemorySize, SMEM_BYTES);
    cudaFuncSetAttribute(hgemm<2>, cudaFuncAttributeMaxDynamicSharedMemorySize, SMEM_BYTES);
    cudaFuncSetAttribute(hgemm<3>, cudaFuncAttributeMaxDynamicSharedMemorySize, SMEM_BYTES);

    const int NPIX = BB * HWP;

    // 1) LN1: x -> h
    ln_kernel<<<NPIX / 256, 256>>>(x, ln1_g, ln1_b, h);

    // 2) qkv GEMM
    {
        dim3 grid(HWP / 128, (C3 + 127) / 128, BB);
        hgemm<0><<<grid, 256, SMEM_BYTES>>>(qkv_w, h, qkv_b, nullptr, qkv, C3, CC);
    }

    // 3) elementwise attention + softmax (scrambled layout)
    attn_kernel<<<(BB * NH * HWP) / 256, 256>>>(qkv, relb, attn);

    // 4) proj GEMM + bias + shortcut(x) -> x2
    {
        dim3 grid(HWP / 128, (CC + 127) / 128, BB);
        hgemm<1><<<grid, 256, SMEM_BYTES>>>(proj_w, attn, proj_b, x, x2, CC, CC);
    }

    // 5) LN2: x2 -> h
    ln_kernel<<<NPIX / 256, 256>>>(x2, ln2_g, ln2_b, h);

    // 6) fc1 GEMM + GELU -> mlp
    {
        dim3 grid(HWP / 128, (HID + 127) / 128, BB);
        hgemm<2><<<grid, 256, SMEM_BYTES>>>(fc1_w, h, fc1_b, nullptr, mlp, HID, CC);
    }

    // 7) fc2 GEMM + bias + residual(x2) -> out
    {
        dim3 grid(HWP / 128, (CC + 127) / 128, BB);
        hgemm<3><<<grid, 256, SMEM_BYTES>>>(fc2_w, mlp, fc2_b, x2, outp, CC, HID);
    }
}

// round 6
// speedup vs baseline: 2.9902x; 1.0924x over previous
#include <cuda_runtime.h>
#include <math.h>
#include <stdint.h>

// Problem dims (fixed by the dataset)
#define BB   16
#define CC   392
#define HWP  4096          // 64*64 pixels
#define NH   8
#define HD   49            // head dim
#define HID  1568          // 4*C
#define C3   1176          // 3*C

// ---------------- scratch (static device, no allocs) ----------------
__device__ float g_h   [(size_t)BB * CC  * HWP];
__device__ float g_qkv [(size_t)BB * C3  * HWP];
__device__ float g_attn[(size_t)BB * CC  * HWP];
__device__ float g_x2  [(size_t)BB * CC  * HWP];
__device__ float g_mlp [(size_t)BB * HID * HWP];

// ================= helpers =================
__device__ __forceinline__ uint32_t smem_u32(const void* p) {
    uint32_t a;
    asm("{ .reg .u64 t; cvta.to.shared.u64 t, %1; cvt.u32.u64 %0, t; }"
        : "=r"(a) : "l"(p));
    return a;
}
__device__ __forceinline__ void cp16(uint32_t saddr, const float* g, bool valid) {
    unsigned long long ga;
    asm("cvta.to.global.u64 %0, %1;" : "=l"(ga) : "l"(g));
    int sz = valid ? 16 : 0;
    asm volatile("cp.async.cg.shared.global [%0], [%1], 16, %2;"
                 :: "r"(saddr), "l"(ga), "r"(sz));
}
#define CP_COMMIT() asm volatile("cp.async.commit_group;" ::: "memory")
#define CP_WAIT2()  asm volatile("cp.async.wait_group 2;" ::: "memory")

// Raw fp32 bits as tf32 operand: HMMA reads the top 19 bits (RZ truncation).
// Saves one F2FP per fragment element (~96 issue slots per warp per K-chunk).
__device__ __forceinline__ uint32_t f2tf32(float f) {
    return __float_as_uint(f);
}
__device__ __forceinline__ void mma_tf32(float* d, const uint32_t* a, const uint32_t* b) {
    asm volatile(
        "mma.sync.aligned.m16n8k8.row.col.f32.tf32.tf32.f32 "
        "{%0,%1,%2,%3}, {%4,%5,%6,%7}, {%8,%9}, {%0,%1,%2,%3};"
        : "+f"(d[0]), "+f"(d[1]), "+f"(d[2]), "+f"(d[3])
        : "r"(a[0]), "r"(a[1]), "r"(a[2]), "r"(a[3]), "r"(b[0]), "r"(b[1]));
}

// ================= HMMA tf32 GEMM =================
// D[o, p] = sum_k W[o][k] * X[k][p].  M = 128 out-channels, N = 128 pixels.
// A smem: [128 o][36 f] (32 k + 4 pad)   = 18432 B
// B smem: [32 k][136 f] (128 p + 8 pad)  = 17408 B
// 3 stages, stage stride 35840 B (8960 floats).
#define KT        32
#define STAGES    3
#define A_STRIDE  36
#define B_STRIDE  136
#define A_FLOATS  4608            // 128*36
#define STAGE_F   8960            // floats per stage
#define STAGE_B   35840           // bytes per stage
#define SMEM_BYTES (STAGES * STAGE_B)

template<int MODE>   // 0:+bias  1:+bias+res  2:+bias+GELU  3:+bias+res
__global__ void __launch_bounds__(256, 2)
hgemm(const float* __restrict__ Wt, const float* __restrict__ X,
      const float* __restrict__ bias, const float* __restrict__ res,
      float* __restrict__ out, int O, int K)
{
    extern __shared__ float smf[];
    const uint32_t sb = smem_u32(smf);
    const int tid  = threadIdx.x;
    const int wid  = tid >> 5;
    const int lane = tid & 31;
    const int r = lane >> 2;          // 0..7
    const int c = lane & 3;           // 0..3
    const int warp_m = (wid >> 2) * 64;   // 0 / 64
    const int warp_n = (wid & 3) * 32;    // 0..96

    const int b  = blockIdx.z;
    const int n0 = blockIdx.x * 128;      // pixel tile
    const int m0 = blockIdx.y * 128;      // out-channel tile
    const float* Xb = X + (size_t)b * K * HWP;
    float*       Ob = out + (size_t)b * O * HWP;
    const float* Rb = (MODE == 1 || MODE == 3) ? res + (size_t)b * O * HWP : nullptr;

    // valid output rows for this CTA / this warp (skip dead 16-row MMA tiles)
    const int mvalid = (O - m0 < 128) ? (O - m0) : 128;
    const int rows_w = mvalid - warp_m;       // warp-uniform

    const int NC = (K + KT - 1) / KT;

    // ---- stage loader (pure cp.async copies) ----
    auto load_stage = [&](int stage, int k0) {
        uint32_t a_base = sb + stage * STAGE_B;
        uint32_t b_base = a_base + 18432;
        #pragma unroll
        for (int i = 0; i < 4; ++i) {               // A: 128 x 32 fl = 1024 x 16B
            int slot = tid + i * 256;
            int row = slot >> 3, kc = slot & 7;
            int o = m0 + row, k = k0 + kc * 4;
            bool v = (o < O) && (k < K);
            cp16(a_base + row * (A_STRIDE * 4) + kc * 16,
                 v ? (Wt + (size_t)o * K + k) : Wt, v);
        }
        #pragma unroll
        for (int i = 0; i < 4; ++i) {               // B: 32 x 128 fl = 1024 x 16B
            int slot = tid + i * 256;
            int kr = slot >> 5, pc = slot & 31;
            int k = k0 + kr;
            bool v = (k < K);
            cp16(b_base + kr * (B_STRIDE * 4) + pc * 16,
                 v ? (Xb + (size_t)k * HWP + n0 + pc * 4) : Xb, v);
        }
    };

    float acc[4][4][4];
    #pragma unroll
    for (int i = 0; i < 4; ++i)
        #pragma unroll
        for (int j = 0; j < 4; ++j)
            #pragma unroll
            for (int t = 0; t < 4; ++t) acc[i][j][t] = 0.f;

    // prologue: stages 0,1
    load_stage(0, 0);           CP_COMMIT();
    if (NC > 1) load_stage(1, KT);
    CP_COMMIT();

    for (int ch = 0; ch < NC; ++ch) {
        int ld = ch + STAGES - 1;
        if (ld < NC) load_stage(ld % STAGES, ld * KT);
        CP_COMMIT();
        CP_WAIT2();
        __syncthreads();

        const float* As = smf + (ch % STAGES) * STAGE_F;
        const float* Bs = As + A_FLOATS;

        if (rows_w > 0) {
            #pragma unroll
            for (int kk = 0; kk < KT; kk += 8) {
                uint32_t af[4][4];
                #pragma unroll
                for (int mt = 0; mt < 4; ++mt) {
                    if (mt * 16 >= rows_w) continue;
                    int row = warp_m + mt * 16 + r;
                    const float* ap = As + row * A_STRIDE + kk + c;
                    af[mt][0] = f2tf32(ap[0]);
                    af[mt][1] = f2tf32(ap[8 * A_STRIDE]);
                    af[mt][2] = f2tf32(ap[4]);
                    af[mt][3] = f2tf32(ap[8 * A_STRIDE + 4]);
                }
                uint32_t bf[4][2];
                #pragma unroll
                for (int nt = 0; nt < 4; ++nt) {
                    int col = warp_n + nt * 8 + r;
                    const float* bp = Bs + (kk + c) * B_STRIDE + col;
                    bf[nt][0] = f2tf32(bp[0]);
                    bf[nt][1] = f2tf32(bp[4 * B_STRIDE]);
                }
                #pragma unroll
                for (int mt = 0; mt < 4; ++mt) {
                    if (mt * 16 >= rows_w) continue;
                    #pragma unroll
                    for (int nt = 0; nt < 4; ++nt)
                        mma_tf32(acc[mt][nt], af[mt], bf[nt]);
                }
            }
        }
        __syncthreads();
    }

    // ---- epilogue: registers -> gmem (float2, consecutive pixels) ----
    #pragma unroll
    for (int mt = 0; mt < 4; ++mt) {
        #pragma unroll
        for (int half = 0; half < 2; ++half) {
            int o = m0 + warp_m + mt * 16 + half * 8 + r;
            if (o >= O) continue;
            float bv = bias[o];
            #pragma unroll
            for (int nt = 0; nt < 4; ++nt) {
                int p = n0 + warp_n + nt * 8 + c * 2;
                float v0 = acc[mt][nt][half * 2 + 0] + bv;
                float v1 = acc[mt][nt][half * 2 + 1] + bv;
                if (MODE == 1 || MODE == 3) {
                    float2 rv = *reinterpret_cast<const float2*>(
                                    Rb + (size_t)o * HWP + p);
                    v0 += rv.x; v1 += rv.y;
                }
                if (MODE == 2) {
                    v0 = 0.5f * v0 * (1.0f + erff(v0 * 0.70710678118654752f));
                    v1 = 0.5f * v1 * (1.0f + erff(v1 * 0.70710678118654752f));
                }
                *reinterpret_cast<float2*>(Ob + (size_t)o * HWP + p)
                    = make_float2(v0, v1);
            }
        }
    }
}

// ---------------- channel LayerNorm over C per pixel ----------------
__global__ void __launch_bounds__(256) ln_kernel(
    const float* __restrict__ x, const float* __restrict__ gma,
    const float* __restrict__ bta, float* __restrict__ out)
{
    int idx = blockIdx.x * blockDim.x + threadIdx.x;
    int b = idx / HWP;
    int p = idx - b * HWP;
    const float* xb = x + (size_t)b * CC * HWP + p;
    float s = 0.f, s2 = 0.f;
    #pragma unroll 8
    for (int c = 0; c < CC; c++) {
        float v = xb[(size_t)c * HWP];
        s += v; s2 += v * v;
    }
    float mu  = s * (1.0f / CC);
    float var = s2 * (1.0f / CC) - mu * mu;
    float inv = rsqrtf(var + 1e-5f);
    float* ob = out + (size_t)b * CC * HWP + p;
    #pragma unroll 8
    for (int c = 0; c < CC; c++) {
        ob[(size_t)c * HWP] = (xb[(size_t)c * HWP] - mu) * inv * gma[c] + bta[c];
    }
}

// ---------------- elementwise attention + softmax over hd ----------------
__global__ void __launch_bounds__(256) attn_kernel(
    const float* __restrict__ qkv, const float* __restrict__ rel_bias,
    float* __restrict__ out)
{
    int gid = blockIdx.x * blockDim.x + threadIdx.x;
    int p  = gid & (HWP - 1);
    int bh = gid / HWP;
    int head = bh & (NH - 1);
    int b = bh / NH;

    const float* base = qkv + (size_t)b * C3 * HWP;
    const float* qp = base + (size_t)(head * HD) * HWP + p;
    const float* kp = base + (size_t)(CC + head * HD) * HWP + p;
    const float* vp = base + (size_t)(2 * CC + head * HD) * HWP + p;
    const float scale = 0.14285714285714285f;   // 49^-0.5

    float s[HD];
    float mx = -INFINITY;
    #pragma unroll
    for (int d = 0; d < HD; d++) {
        float sv = qp[(size_t)d * HWP] * scale * kp[(size_t)d * HWP]
                   + rel_bias[head * HD + d];
        s[d] = sv;
        mx = fmaxf(mx, sv);
    }
    float sum = 0.f;
    #pragma unroll
    for (int d = 0; d < HD; d++) {
        float e = expf(s[d] - mx);
        s[d] = e;
        sum += e;
    }
    float inv = 1.0f / sum;
    float* ob = out + (size_t)b * CC * HWP
                    + (size_t)head * HWP * HD + (size_t)p * HD;
    #pragma unroll
    for (int d = 0; d < HD; d++) {
        ob[d] = s[d] * inv * vp[(size_t)d * HWP];
    }
}

// ---------------- launch ----------------
extern "C" void kernel_launch(void* const* d_in, const int* in_sizes, int n_in,
                              void* d_out, int out_size)
{
    const float* x      = (const float*)d_in[0];
    const float* ln1_g  = (const float*)d_in[1];
    const float* ln1_b  = (const float*)d_in[2];
    const float* qkv_w  = (const float*)d_in[3];
    const float* qkv_b  = (const float*)d_in[4];
    const float* relb   = (const float*)d_in[5];
    const float* proj_w = (const float*)d_in[6];
    const float* proj_b = (const float*)d_in[7];
    const float* ln2_g  = (const float*)d_in[8];
    const float* ln2_b  = (const float*)d_in[9];
    const float* fc1_w  = (const float*)d_in[10];
    const float* fc1_b  = (const float*)d_in[11];
    const float* fc2_w  = (const float*)d_in[12];
    const float* fc2_b  = (const float*)d_in[13];
    float* outp = (float*)d_out;

    float *h, *qkv, *attn, *x2, *mlp;
    cudaGetSymbolAddress((void**)&h,    g_h);
    cudaGetSymbolAddress((void**)&qkv,  g_qkv);
    cudaGetSymbolAddress((void**)&attn, g_attn);
    cudaGetSymbolAddress((void**)&x2,   g_x2);
    cudaGetSymbolAddress((void**)&mlp,  g_mlp);

    cudaFuncSetAttribute(hgemm<0>, cudaFuncAttributeMaxDynamicSharedMemorySize, SMEM_BYTES);
    cudaFuncSetAttribute(hgemm<1>, cudaFuncAttributeMaxDynamicSharedMemorySize, SMEM_BYTES);
    cudaFuncSetAttribute(hgemm<2>, cudaFuncAttributeMaxDynamicSharedMemorySize, SMEM_BYTES);
    cudaFuncSetAttribute(hgemm<3>, cudaFuncAttributeMaxDynamicSharedMemorySize, SMEM_BYTES);

    const int NPIX = BB * HWP;

    // 1) LN1: x -> h
    ln_kernel<<<NPIX / 256, 256>>>(x, ln1_g, ln1_b, h);

    // 2) qkv GEMM
    {
        dim3 grid(HWP / 128, (C3 + 127) / 128, BB);
        hgemm<0><<<grid, 256, SMEM_BYTES>>>(qkv_w, h, qkv_b, nullptr, qkv, C3, CC);
    }

    // 3) elementwise attention + softmax (scrambled layout)
    attn_kernel<<<(BB * NH * HWP) / 256, 256>>>(qkv, relb, attn);

    // 4) proj GEMM + bias + shortcut(x) -> x2
    {
        dim3 grid(HWP / 128, (CC + 127) / 128, BB);
        hgemm<1><<<grid, 256, SMEM_BYTES>>>(proj_w, attn, proj_b, x, x2, CC, CC);
    }

    // 5) LN2: x2 -> h
    ln_kernel<<<NPIX / 256, 256>>>(x2, ln2_g, ln2_b, h);

    // 6) fc1 GEMM + GELU -> mlp
    {
        dim3 grid(HWP / 128, (HID + 127) / 128, BB);
        hgemm<2><<<grid, 256, SMEM_BYTES>>>(fc1_w, h, fc1_b, nullptr, mlp, HID, CC);
    }

    // 7) fc2 GEMM + bias + residual(x2) -> out
    {
        dim3 grid(HWP / 128, (CC + 127) / 128, BB);
        hgemm<3><<<grid, 256, SMEM_BYTES>>>(fc2_w, mlp, fc2_b, x2, outp, CC, HID);
    }
}

// round 7
// speedup vs baseline: 3.2083x; 1.0730x over previous
#include <cuda_runtime.h>
#include <math.h>
#include <stdint.h>

// Problem dims (fixed by the dataset)
#define BB   16
#define CC   392
#define HWP  4096          // 64*64 pixels
#define NH   8
#define HD   49            // head dim
#define HID  1568          // 4*C
#define C3   1176          // 3*C

// ---------------- scratch (static device, no allocs) ----------------
__device__ float g_qkv [(size_t)BB * C3  * HWP];
__device__ float g_attn[(size_t)BB * CC  * HWP];
__device__ float g_x2  [(size_t)BB * CC  * HWP];
__device__ float g_mlp [(size_t)BB * HID * HWP];
__device__ float g_w1p [(size_t)C3  * CC];     // qkv_w * ln1_g
__device__ float g_w2p [(size_t)HID * CC];     // fc1_w * ln2_g
__device__ float g_s1  [C3],  g_cb1[C3];
__device__ float g_s2  [HID], g_cb2[HID];
__device__ float g_mu1 [(size_t)BB * HWP], g_iv1[(size_t)BB * HWP];
__device__ float g_mu2 [(size_t)BB * HWP], g_iv2[(size_t)BB * HWP];

// ================= helpers =================
__device__ __forceinline__ uint32_t smem_u32(const void* p) {
    uint32_t a;
    asm("{ .reg .u64 t; cvta.to.shared.u64 t, %1; cvt.u32.u64 %0, t; }"
        : "=r"(a) : "l"(p));
    return a;
}
__device__ __forceinline__ void cp16(uint32_t saddr, const float* g, bool valid) {
    unsigned long long ga;
    asm("cvta.to.global.u64 %0, %1;" : "=l"(ga) : "l"(g));
    int sz = valid ? 16 : 0;
    asm volatile("cp.async.cg.shared.global [%0], [%1], 16, %2;"
                 :: "r"(saddr), "l"(ga), "r"(sz));
}
#define CP_COMMIT() asm volatile("cp.async.commit_group;" ::: "memory")
#define CP_WAIT1()  asm volatile("cp.async.wait_group 1;" ::: "memory")

// Raw fp32 bits as tf32 operand (HW truncates to top 19 bits).
__device__ __forceinline__ uint32_t f2tf32(float f) {
    return __float_as_uint(f);
}
__device__ __forceinline__ void mma_tf32(float* d, const uint32_t* a, const uint32_t* b) {
    asm volatile(
        "mma.sync.aligned.m16n8k8.row.col.f32.tf32.tf32.f32 "
        "{%0,%1,%2,%3}, {%4,%5,%6,%7}, {%8,%9}, {%0,%1,%2,%3};"
        : "+f"(d[0]), "+f"(d[1]), "+f"(d[2]), "+f"(d[3])
        : "r"(a[0]), "r"(a[1]), "r"(a[2]), "r"(a[3]), "r"(b[0]), "r"(b[1]));
}

// ================= HMMA tf32 GEMM =================
// D[o, p] = sum_k W[o][k] * X[k][p].  M = 128 out-channels, N = 128 pixels.
// A smem: [128 o][36 f]   B smem: [32 k][136 f]   3 stages.
#define KT        32
#define STAGES    3
#define A_STRIDE  36
#define B_STRIDE  136
#define A_FLOATS  4608            // 128*36
#define STAGE_F   8960
#define STAGE_B   35840
#define SMEM_BYTES (STAGES * STAGE_B)

// MODE: 1 = +bias+res (proj)   3 = +bias+res (fc2)
//       4 = LN-fold (qkv)      5 = LN-fold + exact GELU (fc1)
template<int MODE>
__global__ void __launch_bounds__(256, 2)
hgemm(const float* __restrict__ Wt, const float* __restrict__ X,
      const float* __restrict__ bias, const float* __restrict__ res,
      float* __restrict__ out, int O, int K,
      const float* __restrict__ sarr,
      const float* __restrict__ mu, const float* __restrict__ inv)
{
    extern __shared__ float smf[];
    const uint32_t sb = smem_u32(smf);
    const int tid  = threadIdx.x;
    const int wid  = tid >> 5;
    const int lane = tid & 31;
    const int r = lane >> 2;
    const int c = lane & 3;
    const int warp_m = (wid >> 2) * 64;
    const int warp_n = (wid & 3) * 32;

    const int b  = blockIdx.z;
    const int n0 = blockIdx.x * 128;
    const int m0 = blockIdx.y * 128;
    const float* Xb = X + (size_t)b * K * HWP;
    float*       Ob = out + (size_t)b * O * HWP;
    const float* Rb = (MODE == 1 || MODE == 3) ? res + (size_t)b * O * HWP : nullptr;

    const int mvalid = (O - m0 < 128) ? (O - m0) : 128;
    const int rows_w = mvalid - warp_m;        // warp-uniform

    const int NC = (K + KT - 1) / KT;

    auto load_stage = [&](int stage, int k0) {
        uint32_t a_base = sb + stage * STAGE_B;
        uint32_t b_base = a_base + 18432;
        #pragma unroll
        for (int i = 0; i < 4; ++i) {               // A: 128 x 32 fl
            int slot = tid + i * 256;
            int row = slot >> 3, kc = slot & 7;
            int o = m0 + row, k = k0 + kc * 4;
            bool v = (o < O) && (k < K);
            cp16(a_base + row * (A_STRIDE * 4) + kc * 16,
                 v ? (Wt + (size_t)o * K + k) : Wt, v);
        }
        #pragma unroll
        for (int i = 0; i < 4; ++i) {               // B: 32 x 128 fl
            int slot = tid + i * 256;
            int kr = slot >> 5, pc = slot & 31;
            int k = k0 + kr;
            bool v = (k < K);
            cp16(b_base + kr * (B_STRIDE * 4) + pc * 16,
                 v ? (Xb + (size_t)k * HWP + n0 + pc * 4) : Xb, v);
        }
    };

    float acc[4][4][4];
    #pragma unroll
    for (int i = 0; i < 4; ++i)
        #pragma unroll
        for (int j = 0; j < 4; ++j)
            #pragma unroll
            for (int t = 0; t < 4; ++t) acc[i][j][t] = 0.f;

    // prologue: stages 0,1 in flight
    load_stage(0, 0);           CP_COMMIT();
    if (NC > 1) load_stage(1, KT);
    CP_COMMIT();

    for (int ch = 0; ch < NC; ++ch) {
        // entering iter ch: groups for stages ch, ch+1 outstanding
        CP_WAIT1();               // stage ch complete
        __syncthreads();          // visible to all; all readers of stage ch-1 done

        int ld = ch + 2;
        if (ld < NC) load_stage(ld % STAGES, ld * KT);
        CP_COMMIT();              // always exactly one group per iter (may be empty)

        const float* As = smf + (ch % STAGES) * STAGE_F;
        const float* Bs = As + A_FLOATS;

        if (rows_w > 0) {
            #pragma unroll
            for (int kk = 0; kk < KT; kk += 8) {
                uint32_t af[4][4];
                #pragma unroll
                for (int mt = 0; mt < 4; ++mt) {
                    if (mt * 16 >= rows_w) continue;
                    int row = warp_m + mt * 16 + r;
                    const float* ap = As + row * A_STRIDE + kk + c;
                    af[mt][0] = f2tf32(ap[0]);
                    af[mt][1] = f2tf32(ap[8 * A_STRIDE]);
                    af[mt][2] = f2tf32(ap[4]);
                    af[mt][3] = f2tf32(ap[8 * A_STRIDE + 4]);
                }
                uint32_t bf[4][2];
                #pragma unroll
                for (int nt = 0; nt < 4; ++nt) {
                    int col = warp_n + nt * 8 + r;
                    const float* bp = Bs + (kk + c) * B_STRIDE + col;
                    bf[nt][0] = f2tf32(bp[0]);
                    bf[nt][1] = f2tf32(bp[4 * B_STRIDE]);
                }
                #pragma unroll
                for (int mt = 0; mt < 4; ++mt) {
                    if (mt * 16 >= rows_w) continue;
                    #pragma unroll
                    for (int nt = 0; nt < 4; ++nt)
                        mma_tf32(acc[mt][nt], af[mt], bf[nt]);
                }
            }
        }
    }

    // ---- epilogue ----
    float2 m2[4], i2[4];
    if (MODE >= 4) {
        const float* muB = mu  + (size_t)b * HWP + n0;
        const float* ivB = inv + (size_t)b * HWP + n0;
        #pragma unroll
        for (int nt = 0; nt < 4; ++nt) {
            int p = warp_n + nt * 8 + c * 2;
            m2[nt] = *reinterpret_cast<const float2*>(muB + p);
            i2[nt] = *reinterpret_cast<const float2*>(ivB + p);
        }
    }
    #pragma unroll
    for (int mt = 0; mt < 4; ++mt) {
        #pragma unroll
        for (int half = 0; half < 2; ++half) {
            int o = m0 + warp_m + mt * 16 + half * 8 + r;
            if (o >= O) continue;
            float bv = bias[o];
            float so = (MODE >= 4) ? sarr[o] : 0.f;
            #pragma unroll
            for (int nt = 0; nt < 4; ++nt) {
                int p = n0 + warp_n + nt * 8 + c * 2;
                float v0 = acc[mt][nt][half * 2 + 0];
                float v1 = acc[mt][nt][half * 2 + 1];
                if (MODE == 1 || MODE == 3) {
                    float2 rv = *reinterpret_cast<const float2*>(
                                    Rb + (size_t)o * HWP + p);
                    v0 += bv + rv.x; v1 += bv + rv.y;
                } else {
                    // LN fold: inv*(acc - mu*s) + cb
                    v0 = i2[nt].x * (v0 - m2[nt].x * so) + bv;
                    v1 = i2[nt].y * (v1 - m2[nt].y * so) + bv;
                    if (MODE == 5) {
                        v0 = 0.5f * v0 * (1.0f + erff(v0 * 0.70710678118654752f));
                        v1 = 0.5f * v1 * (1.0f + erff(v1 * 0.70710678118654752f));
                    }
                }
                *reinterpret_cast<float2*>(Ob + (size_t)o * HWP + p)
                    = make_float2(v0, v1);
            }
        }
    }
}

// ---------------- LN stats: per-pixel mu, inv ----------------
__global__ void __launch_bounds__(256) ln_stats(
    const float* __restrict__ x, float* __restrict__ mu, float* __restrict__ inv)
{
    int idx = blockIdx.x * blockDim.x + threadIdx.x;
    int b = idx / HWP;
    int p = idx - b * HWP;
    const float* xb = x + (size_t)b * CC * HWP + p;
    float s = 0.f, s2 = 0.f;
    #pragma unroll 8
    for (int c = 0; c < CC; c++) {
        float v = xb[(size_t)c * HWP];
        s += v; s2 += v * v;
    }
    float m  = s * (1.0f / CC);
    float var = s2 * (1.0f / CC) - m * m;
    mu[idx]  = m;
    inv[idx] = rsqrtf(var + 1e-5f);
}

// ---------------- weight prep: W' = W*g, s = rowsum(W'), cb = bias + W@beta ----
__global__ void __launch_bounds__(256) prep_w(
    const float* __restrict__ W, const float* __restrict__ g,
    const float* __restrict__ bta, const float* __restrict__ bias,
    float* __restrict__ Wp, float* __restrict__ sarr, float* __restrict__ cb,
    int O, int K)
{
    int w = (blockIdx.x * 256 + threadIdx.x) >> 5;
    int lane = threadIdx.x & 31;
    if (w >= O) return;
    float ss = 0.f, bs = 0.f;
    for (int k = lane; k < K; k += 32) {
        float wv = W[(size_t)w * K + k];
        float wp = wv * g[k];
        Wp[(size_t)w * K + k] = wp;
        ss += wp;
        bs += wv * bta[k];
    }
    #pragma unroll
    for (int off = 16; off; off >>= 1) {
        ss += __shfl_xor_sync(0xFFFFFFFFu, ss, off);
        bs += __shfl_xor_sync(0xFFFFFFFFu, bs, off);
    }
    if (lane == 0) { sarr[w] = ss; cb[w] = bias[w] + bs; }
}

// ---------------- elementwise attention + softmax over hd ----------------
__global__ void __launch_bounds__(256) attn_kernel(
    const float* __restrict__ qkv, const float* __restrict__ rel_bias,
    float* __restrict__ out)
{
    int gid = blockIdx.x * blockDim.x + threadIdx.x;
    int p  = gid & (HWP - 1);
    int bh = gid / HWP;
    int head = bh & (NH - 1);
    int b = bh / NH;

    const float* base = qkv + (size_t)b * C3 * HWP;
    const float* qp = base + (size_t)(head * HD) * HWP + p;
    const float* kp = base + (size_t)(CC + head * HD) * HWP + p;
    const float* vp = base + (size_t)(2 * CC + head * HD) * HWP + p;
    const float scale = 0.14285714285714285f;   // 49^-0.5

    float s[HD];
    float mx = -INFINITY;
    #pragma unroll
    for (int d = 0; d < HD; d++) {
        float sv = qp[(size_t)d * HWP] * scale * kp[(size_t)d * HWP]
                   + rel_bias[head * HD + d];
        s[d] = sv;
        mx = fmaxf(mx, sv);
    }
    float sum = 0.f;
    #pragma unroll
    for (int d = 0; d < HD; d++) {
        float e = expf(s[d] - mx);
        s[d] = e;
        sum += e;
    }
    float inv = 1.0f / sum;
    float* ob = out + (size_t)b * CC * HWP
                    + (size_t)head * HWP * HD + (size_t)p * HD;
    #pragma unroll
    for (int d = 0; d < HD; d++) {
        ob[d] = s[d] * inv * vp[(size_t)d * HWP];
    }
}

// ---------------- launch ----------------
extern "C" void kernel_launch(void* const* d_in, const int* in_sizes, int n_in,
                              void* d_out, int out_size)
{
    const float* x      = (const float*)d_in[0];
    const float* ln1_g  = (const float*)d_in[1];
    const float* ln1_b  = (const float*)d_in[2];
    const float* qkv_w  = (const float*)d_in[3];
    const float* qkv_b  = (const float*)d_in[4];
    const float* relb   = (const float*)d_in[5];
    const float* proj_w = (const float*)d_in[6];
    const float* proj_b = (const float*)d_in[7];
    const float* ln2_g  = (const float*)d_in[8];
    const float* ln2_b  = (const float*)d_in[9];
    const float* fc1_w  = (const float*)d_in[10];
    const float* fc1_b  = (const float*)d_in[11];
    const float* fc2_w  = (const float*)d_in[12];
    const float* fc2_b  = (const float*)d_in[13];
    float* outp = (float*)d_out;

    float *qkv, *attn, *x2, *mlp, *w1p, *w2p, *s1, *cb1, *s2, *cb2;
    float *mu1, *iv1, *mu2, *iv2;
    cudaGetSymbolAddress((void**)&qkv,  g_qkv);
    cudaGetSymbolAddress((void**)&attn, g_attn);
    cudaGetSymbolAddress((void**)&x2,   g_x2);
    cudaGetSymbolAddress((void**)&mlp,  g_mlp);
    cudaGetSymbolAddress((void**)&w1p,  g_w1p);
    cudaGetSymbolAddress((void**)&w2p,  g_w2p);
    cudaGetSymbolAddress((void**)&s1,   g_s1);
    cudaGetSymbolAddress((void**)&cb1,  g_cb1);
    cudaGetSymbolAddress((void**)&s2,   g_s2);
    cudaGetSymbolAddress((void**)&cb2,  g_cb2);
    cudaGetSymbolAddress((void**)&mu1,  g_mu1);
    cudaGetSymbolAddress((void**)&iv1,  g_iv1);
    cudaGetSymbolAddress((void**)&mu2,  g_mu2);
    cudaGetSymbolAddress((void**)&iv2,  g_iv2);

    cudaFuncSetAttribute(hgemm<1>, cudaFuncAttributeMaxDynamicSharedMemorySize, SMEM_BYTES);
    cudaFuncSetAttribute(hgemm<3>, cudaFuncAttributeMaxDynamicSharedMemorySize, SMEM_BYTES);
    cudaFuncSetAttribute(hgemm<4>, cudaFuncAttributeMaxDynamicSharedMemorySize, SMEM_BYTES);
    cudaFuncSetAttribute(hgemm<5>, cudaFuncAttributeMaxDynamicSharedMemorySize, SMEM_BYTES);

    const int NPIX = BB * HWP;

    // 0) weight prep (tiny) + LN1 stats
    prep_w<<<(C3 * 32 + 255) / 256, 256>>>(qkv_w, ln1_g, ln1_b, qkv_b,
                                           w1p, s1, cb1, C3, CC);
    prep_w<<<(HID * 32 + 255) / 256, 256>>>(fc1_w, ln2_g, ln2_b, fc1_b,
                                            w2p, s2, cb2, HID, CC);
    ln_stats<<<NPIX / 256, 256>>>(x, mu1, iv1);

    // 1) qkv GEMM with fused LN1 (reads raw x)
    {
        dim3 grid(HWP / 128, (C3 + 127) / 128, BB);
        hgemm<4><<<grid, 256, SMEM_BYTES>>>(w1p, x, cb1, nullptr, qkv, C3, CC,
                                            s1, mu1, iv1);
    }

    // 2) elementwise attention + softmax (scrambled layout)
    attn_kernel<<<(BB * NH * HWP) / 256, 256>>>(qkv, relb, attn);

    // 3) proj GEMM + bias + shortcut(x) -> x2
    {
        dim3 grid(HWP / 128, (CC + 127) / 128, BB);
        hgemm<1><<<grid, 256, SMEM_BYTES>>>(proj_w, attn, proj_b, x, x2, CC, CC,
                                            nullptr, nullptr, nullptr);
    }

    // 4) LN2 stats on x2
    ln_stats<<<NPIX / 256, 256>>>(x2, mu2, iv2);

    // 5) fc1 GEMM with fused LN2 + GELU (reads raw x2)
    {
        dim3 grid(HWP / 128, (HID + 127) / 128, BB);
        hgemm<5><<<grid, 256, SMEM_BYTES>>>(w2p, x2, cb2, nullptr, mlp, HID, CC,
                                            s2, mu2, iv2);
    }

    // 6) fc2 GEMM + bias + residual(x2) -> out
    {
        dim3 grid(HWP / 128, (CC + 127) / 128, BB);
        hgemm<3><<<grid, 256, SMEM_BYTES>>>(fc2_w, mlp, fc2_b, x2, outp, CC, HID,
                                            nullptr, nullptr, nullptr);
    }
}

// round 8
// speedup vs baseline: 3.6293x; 1.1312x over previous
#include <cuda_runtime.h>
#include <math.h>
#include <stdint.h>

// Problem dims (fixed by the dataset)
#define BB   16
#define CC   392
#define HWP  4096          // 64*64 pixels
#define NH   8
#define HD   49            // head dim
#define HID  1568          // 4*C
#define C3   1176          // 3*C

#define KT   32
#define KC_C    13         // ceil(392/32)
#define KC_HID  49         // 1568/32
#define MT_QKV  10         // ceil(1176/128)
#define MT_C    4          // ceil(392/128)  (proj, fc2 outputs)
#define MT_HID  13         // ceil(1568/128)

// ---------------- scratch (static device, no allocs) ----------------
__device__ float g_qkv [(size_t)BB * C3  * HWP];
__device__ float g_attn[(size_t)BB * CC  * HWP];
__device__ float g_x2  [(size_t)BB * CC  * HWP];
__device__ float g_mlp [(size_t)BB * HID * HWP];
// fragment-permuted weights: [mtile][kchunk][kk(4)][mb(8)][lane(32)][4]
__device__ float g_w1p [(size_t)MT_QKV * KC_C   * 4096];   // qkv  (× ln1_g)
__device__ float g_wpp [(size_t)MT_C   * KC_C   * 4096];   // proj
__device__ float g_w2p [(size_t)MT_HID * KC_C   * 4096];   // fc1  (× ln2_g)
__device__ float g_w3p [(size_t)MT_C   * KC_HID * 4096];   // fc2
__device__ float g_s1  [C3],  g_cb1[C3];
__device__ float g_s2  [HID], g_cb2[HID];
__device__ float g_mu1 [(size_t)BB * HWP], g_iv1[(size_t)BB * HWP];
__device__ float g_mu2 [(size_t)BB * HWP], g_iv2[(size_t)BB * HWP];

// ================= helpers =================
__device__ __forceinline__ uint32_t smem_u32(const void* p) {
    uint32_t a;
    asm("{ .reg .u64 t; cvta.to.shared.u64 t, %1; cvt.u32.u64 %0, t; }"
        : "=r"(a) : "l"(p));
    return a;
}
__device__ __forceinline__ void cp16(uint32_t saddr, const float* g, bool valid) {
    unsigned long long ga;
    asm("cvta.to.global.u64 %0, %1;" : "=l"(ga) : "l"(g));
    int sz = valid ? 16 : 0;
    asm volatile("cp.async.cg.shared.global [%0], [%1], 16, %2;"
                 :: "r"(saddr), "l"(ga), "r"(sz));
}
#define CP_COMMIT() asm volatile("cp.async.commit_group;" ::: "memory")
#define CP_WAIT1()  asm volatile("cp.async.wait_group 1;" ::: "memory")

__device__ __forceinline__ void mma_tf32(float* d, const uint32_t* a, const uint32_t* b) {
    asm volatile(
        "mma.sync.aligned.m16n8k8.row.col.f32.tf32.tf32.f32 "
        "{%0,%1,%2,%3}, {%4,%5,%6,%7}, {%8,%9}, {%0,%1,%2,%3};"
        : "+f"(d[0]), "+f"(d[1]), "+f"(d[2]), "+f"(d[3])
        : "r"(a[0]), "r"(a[1]), "r"(a[2]), "r"(a[3]), "r"(b[0]), "r"(b[1]));
}

// ================= HMMA tf32 GEMM (fragment-permuted A) =================
// D[o, p] = sum_k W[o][k] * X[k][p].  M = 128 out-channels, N = 128 pixels.
// smem per stage: A 16384 B (fragment order) + B [32 k][136 f] 17408 B.
#define STAGES    3
#define B_STRIDE  136
#define STAGE_F   8448            // floats per stage
#define STAGE_B   33792           // bytes per stage
#define SMEM_BYTES (STAGES * STAGE_B)

// MODE: 1 = +bias+res (proj)   3 = +bias+res (fc2)
//       4 = LN-fold (qkv)      5 = LN-fold + exact GELU (fc1)
template<int MODE>
__global__ void __launch_bounds__(256, 2)
hgemm(const float* __restrict__ Wp, const float* __restrict__ X,
      const float* __restrict__ bias, const float* __restrict__ res,
      float* __restrict__ out, int O, int K,
      const float* __restrict__ sarr,
      const float* __restrict__ mu, const float* __restrict__ inv)
{
    extern __shared__ float smf[];
    const uint32_t sb = smem_u32(smf);
    const int tid  = threadIdx.x;
    const int wid  = tid >> 5;
    const int lane = tid & 31;
    const int r = lane >> 2;
    const int c = lane & 3;
    const int warp_m = (wid >> 2) * 64;
    const int warp_n = (wid & 3) * 32;
    const int mb0 = warp_m >> 4;           // 0 or 4

    const int b  = blockIdx.z;
    const int n0 = blockIdx.x * 128;
    const int m0 = blockIdx.y * 128;
    const float* Xb = X + (size_t)b * K * HWP;
    float*       Ob = out + (size_t)b * O * HWP;
    const float* Rb = (MODE == 1 || MODE == 3) ? res + (size_t)b * O * HWP : nullptr;

    const int mvalid = (O - m0 < 128) ? (O - m0) : 128;
    const int rows_w = mvalid - warp_m;        // warp-uniform

    const int NC = (K + KT - 1) / KT;

    auto load_stage = [&](int stage, int ch) {
        uint32_t a_base = sb + stage * STAGE_B;
        uint32_t b_base = a_base + 16384;
        const float* wsrc = Wp + ((size_t)blockIdx.y * NC + ch) * 4096;
        #pragma unroll
        for (int i = 0; i < 4; ++i) {               // A: contiguous 16 KB
            int slot = tid + i * 256;
            cp16(a_base + slot * 16, wsrc + slot * 4, true);
        }
        int k0 = ch * KT;
        #pragma unroll
        for (int i = 0; i < 4; ++i) {               // B: 32 x 128 fl
            int slot = tid + i * 256;
            int kr = slot >> 5, pc = slot & 31;
            int k = k0 + kr;
            bool v = (k < K);
            cp16(b_base + kr * (B_STRIDE * 4) + pc * 16,
                 v ? (Xb + (size_t)k * HWP + n0 + pc * 4) : Xb, v);
        }
    };

    float acc[4][4][4];
    #pragma unroll
    for (int i = 0; i < 4; ++i)
        #pragma unroll
        for (int j = 0; j < 4; ++j)
            #pragma unroll
            for (int t = 0; t < 4; ++t) acc[i][j][t] = 0.f;

    load_stage(0, 0);           CP_COMMIT();
    if (NC > 1) load_stage(1, 1);
    CP_COMMIT();

    for (int ch = 0; ch < NC; ++ch) {
        CP_WAIT1();               // stage ch complete
        __syncthreads();          // all readers of stage ch-1 done

        int ld = ch + 2;
        if (ld < NC) load_stage(ld % STAGES, ld);
        CP_COMMIT();              // exactly one group per iter

        const float* As = smf + (ch % STAGES) * STAGE_F;
        const float* Bs = As + 4096;

        if (rows_w > 0) {
            #pragma unroll
            for (int kkq = 0; kkq < 4; ++kkq) {
                uint32_t af[4][4];
                #pragma unroll
                for (int mt = 0; mt < 4; ++mt) {
                    if (mt * 16 >= rows_w) continue;
                    uint4 v = *reinterpret_cast<const uint4*>(
                        As + kkq * 1024 + (mb0 + mt) * 128 + lane * 4);
                    af[mt][0] = v.x; af[mt][1] = v.y;
                    af[mt][2] = v.z; af[mt][3] = v.w;
                }
                uint32_t bf[4][2];
                #pragma unroll
                for (int nt = 0; nt < 4; ++nt) {
                    int col = warp_n + nt * 8 + r;
                    const float* bp = Bs + (kkq * 8 + c) * B_STRIDE + col;
                    bf[nt][0] = __float_as_uint(bp[0]);
                    bf[nt][1] = __float_as_uint(bp[4 * B_STRIDE]);
                }
                #pragma unroll
                for (int mt = 0; mt < 4; ++mt) {
                    if (mt * 16 >= rows_w) continue;
                    #pragma unroll
                    for (int nt = 0; nt < 4; ++nt)
                        mma_tf32(acc[mt][nt], af[mt], bf[nt]);
                }
            }
        }
    }

    // ---- epilogue ----
    float2 m2[4], i2[4];
    if (MODE >= 4) {
        const float* muB = mu  + (size_t)b * HWP + n0;
        const float* ivB = inv + (size_t)b * HWP + n0;
        #pragma unroll
        for (int nt = 0; nt < 4; ++nt) {
            int p = warp_n + nt * 8 + c * 2;
            m2[nt] = *reinterpret_cast<const float2*>(muB + p);
            i2[nt] = *reinterpret_cast<const float2*>(ivB + p);
        }
    }
    #pragma unroll
    for (int mt = 0; mt < 4; ++mt) {
        #pragma unroll
        for (int half = 0; half < 2; ++half) {
            int o = m0 + warp_m + mt * 16 + half * 8 + r;
            if (o >= O) continue;
            float bv = bias[o];
            float so = (MODE >= 4) ? sarr[o] : 0.f;
            #pragma unroll
            for (int nt = 0; nt < 4; ++nt) {
                int p = n0 + warp_n + nt * 8 + c * 2;
                float v0 = acc[mt][nt][half * 2 + 0];
                float v1 = acc[mt][nt][half * 2 + 1];
                if (MODE == 1 || MODE == 3) {
                    float2 rv = *reinterpret_cast<const float2*>(
                                    Rb + (size_t)o * HWP + p);
                    v0 += bv + rv.x; v1 += bv + rv.y;
                } else {
                    v0 = i2[nt].x * (v0 - m2[nt].x * so) + bv;
                    v1 = i2[nt].y * (v1 - m2[nt].y * so) + bv;
                    if (MODE == 5) {
                        v0 = 0.5f * v0 * (1.0f + erff(v0 * 0.70710678118654752f));
                        v1 = 0.5f * v1 * (1.0f + erff(v1 * 0.70710678118654752f));
                    }
                }
                *reinterpret_cast<float2*>(Ob + (size_t)o * HWP + p)
                    = make_float2(v0, v1);
            }
        }
    }
}

// ---------------- weight permutation into fragment order ----------------
// Wp group gid = ((((mt*Kc + ch)*4 + kk)*8 + mb)*32 + lane), 4 floats each:
//   (row, col), (row+8, col), (row, col+4), (row+8, col+4)
//   row = mt*128 + mb*16 + r,  col = ch*32 + kk*8 + c   (lane = r*4+c)
__global__ void __launch_bounds__(256) prep_perm(
    const float* __restrict__ W, const float* __restrict__ g,
    float* __restrict__ Wp, int O, int K, int Mt, int Kc)
{
    size_t gid = (size_t)blockIdx.x * 256 + threadIdx.x;
    size_t total = (size_t)Mt * Kc * 1024;
    if (gid >= total) return;
    int lane = gid & 31;
    int mb   = (gid >> 5) & 7;
    int kk   = (gid >> 8) & 3;
    size_t t = gid >> 10;
    int ch = (int)(t % Kc);
    int mt = (int)(t / Kc);
    int r = lane >> 2, c = lane & 3;
    int row = mt * 128 + mb * 16 + r;
    int col = ch * 32 + kk * 8 + c;
    float v0 = 0.f, v1 = 0.f, v2 = 0.f, v3 = 0.f;
    if (col < K) {
        float gv = g ? g[col] : 1.f;
        if (row     < O) v0 = W[(size_t)row * K + col] * gv;
        if (row + 8 < O) v1 = W[(size_t)(row + 8) * K + col] * gv;
        if (col + 4 < K) {
            float gv4 = g ? g[col + 4] : 1.f;
            if (row     < O) v2 = W[(size_t)row * K + col + 4] * gv4;
            if (row + 8 < O) v3 = W[(size_t)(row + 8) * K + col + 4] * gv4;
        }
    }
    float4* dst = reinterpret_cast<float4*>(Wp + gid * 4);
    *dst = make_float4(v0, v1, v2, v3);
}

// ---------------- LN-fold row constants: s = rowsum(W*g), cb = bias + W@beta --
__global__ void __launch_bounds__(256) prep_scb(
    const float* __restrict__ W, const float* __restrict__ g,
    const float* __restrict__ bta, const float* __restrict__ bias,
    float* __restrict__ sarr, float* __restrict__ cb, int O, int K)
{
    int w = (blockIdx.x * 256 + threadIdx.x) >> 5;
    int lane = threadIdx.x & 31;
    if (w >= O) return;
    float ss = 0.f, bs = 0.f;
    for (int k = lane; k < K; k += 32) {
        float wv = W[(size_t)w * K + k];
        ss += wv * g[k];
        bs += wv * bta[k];
    }
    #pragma unroll
    for (int off = 16; off; off >>= 1) {
        ss += __shfl_xor_sync(0xFFFFFFFFu, ss, off);
        bs += __shfl_xor_sync(0xFFFFFFFFu, bs, off);
    }
    if (lane == 0) { sarr[w] = ss; cb[w] = bias[w] + bs; }
}

// ---------------- LN stats: per-pixel mu, inv ----------------
__global__ void __launch_bounds__(256) ln_stats(
    const float* __restrict__ x, float* __restrict__ mu, float* __restrict__ inv)
{
    int idx = blockIdx.x * blockDim.x + threadIdx.x;
    int b = idx / HWP;
    int p = idx - b * HWP;
    const float* xb = x + (size_t)b * CC * HWP + p;
    float s = 0.f, s2 = 0.f;
    #pragma unroll 8
    for (int c = 0; c < CC; c++) {
        float v = xb[(size_t)c * HWP];
        s += v; s2 += v * v;
    }
    float m  = s * (1.0f / CC);
    float var = s2 * (1.0f / CC) - m * m;
    mu[idx]  = m;
    inv[idx] = rsqrtf(var + 1e-5f);
}

// ---------------- elementwise attention + softmax over hd ----------------
__global__ void __launch_bounds__(256) attn_kernel(
    const float* __restrict__ qkv, const float* __restrict__ rel_bias,
    float* __restrict__ out)
{
    int gid = blockIdx.x * blockDim.x + threadIdx.x;
    int p  = gid & (HWP - 1);
    int bh = gid / HWP;
    int head = bh & (NH - 1);
    int b = bh / NH;

    const float* base = qkv + (size_t)b * C3 * HWP;
    const float* qp = base + (size_t)(head * HD) * HWP + p;
    const float* kp = base + (size_t)(CC + head * HD) * HWP + p;
    const float* vp = base + (size_t)(2 * CC + head * HD) * HWP + p;
    const float scale = 0.14285714285714285f;   // 49^-0.5

    float s[HD];
    float mx = -INFINITY;
    #pragma unroll
    for (int d = 0; d < HD; d++) {
        float sv = qp[(size_t)d * HWP] * scale * kp[(size_t)d * HWP]
                   + rel_bias[head * HD + d];
        s[d] = sv;
        mx = fmaxf(mx, sv);
    }
    float sum = 0.f;
    #pragma unroll
    for (int d = 0; d < HD; d++) {
        float e = expf(s[d] - mx);
        s[d] = e;
        sum += e;
    }
    float inv = 1.0f / sum;
    float* ob = out + (size_t)b * CC * HWP
                    + (size_t)head * HWP * HD + (size_t)p * HD;
    #pragma unroll
    for (int d = 0; d < HD; d++) {
        ob[d] = s[d] * inv * vp[(size_t)d * HWP];
    }
}

// ---------------- launch ----------------
extern "C" void kernel_launch(void* const* d_in, const int* in_sizes, int n_in,
                              void* d_out, int out_size)
{
    const float* x      = (const float*)d_in[0];
    const float* ln1_g  = (const float*)d_in[1];
    const float* ln1_b  = (const float*)d_in[2];
    const float* qkv_w  = (const float*)d_in[3];
    const float* qkv_b  = (const float*)d_in[4];
    const float* relb   = (const float*)d_in[5];
    const float* proj_w = (const float*)d_in[6];
    const float* proj_b = (const float*)d_in[7];
    const float* ln2_g  = (const float*)d_in[8];
    const float* ln2_b  = (const float*)d_in[9];
    const float* fc1_w  = (const float*)d_in[10];
    const float* fc1_b  = (const float*)d_in[11];
    const float* fc2_w  = (const float*)d_in[12];
    const float* fc2_b  = (const float*)d_in[13];
    float* outp = (float*)d_out;

    float *qkv, *attn, *x2, *mlp, *w1p, *wpp, *w2p, *w3p;
    float *s1, *cb1, *s2, *cb2, *mu1, *iv1, *mu2, *iv2;
    cudaGetSymbolAddress((void**)&qkv,  g_qkv);
    cudaGetSymbolAddress((void**)&attn, g_attn);
    cudaGetSymbolAddress((void**)&x2,   g_x2);
    cudaGetSymbolAddress((void**)&mlp,  g_mlp);
    cudaGetSymbolAddress((void**)&w1p,  g_w1p);
    cudaGetSymbolAddress((void**)&wpp,  g_wpp);
    cudaGetSymbolAddress((void**)&w2p,  g_w2p);
    cudaGetSymbolAddress((void**)&w3p,  g_w3p);
    cudaGetSymbolAddress((void**)&s1,   g_s1);
    cudaGetSymbolAddress((void**)&cb1,  g_cb1);
    cudaGetSymbolAddress((void**)&s2,   g_s2);
    cudaGetSymbolAddress((void**)&cb2,  g_cb2);
    cudaGetSymbolAddress((void**)&mu1,  g_mu1);
    cudaGetSymbolAddress((void**)&iv1,  g_iv1);
    cudaGetSymbolAddress((void**)&mu2,  g_mu2);
    cudaGetSymbolAddress((void**)&iv2,  g_iv2);

    cudaFuncSetAttribute(hgemm<1>, cudaFuncAttributeMaxDynamicSharedMemorySize, SMEM_BYTES);
    cudaFuncSetAttribute(hgemm<3>, cudaFuncAttributeMaxDynamicSharedMemorySize, SMEM_BYTES);
    cudaFuncSetAttribute(hgemm<4>, cudaFuncAttributeMaxDynamicSharedMemorySize, SMEM_BYTES);
    cudaFuncSetAttribute(hgemm<5>, cudaFuncAttributeMaxDynamicSharedMemorySize, SMEM_BYTES);

    const int NPIX = BB * HWP;

    // 0) weight permutation + LN-fold constants + LN1 stats
    prep_perm<<<(MT_QKV * KC_C * 1024 + 255) / 256, 256>>>(
        qkv_w, ln1_g, w1p, C3, CC, MT_QKV, KC_C);
    prep_perm<<<(MT_C * KC_C * 1024 + 255) / 256, 256>>>(
        proj_w, nullptr, wpp, CC, CC, MT_C, KC_C);
    prep_perm<<<(MT_HID * KC_C * 1024 + 255) / 256, 256>>>(
        fc1_w, ln2_g, w2p, HID, CC, MT_HID, KC_C);
    prep_perm<<<(MT_C * KC_HID * 1024 + 255) / 256, 256>>>(
        fc2_w, nullptr, w3p, CC, HID, MT_C, KC_HID);
    prep_scb<<<(C3 * 32 + 255) / 256, 256>>>(qkv_w, ln1_g, ln1_b, qkv_b,
                                             s1, cb1, C3, CC);
    prep_scb<<<(HID * 32 + 255) / 256, 256>>>(fc1_w, ln2_g, ln2_b, fc1_b,
                                              s2, cb2, HID, CC);
    ln_stats<<<NPIX / 256, 256>>>(x, mu1, iv1);

    // 1) qkv GEMM with fused LN1 (reads raw x)
    {
        dim3 grid(HWP / 128, MT_QKV, BB);
        hgemm<4><<<grid, 256, SMEM_BYTES>>>(w1p, x, cb1, nullptr, qkv, C3, CC,
                                            s1, mu1, iv1);
    }

    // 2) elementwise attention + softmax (scrambled layout)
    attn_kernel<<<(BB * NH * HWP) / 256, 256>>>(qkv, relb, attn);

    // 3) proj GEMM + bias + shortcut(x) -> x2
    {
        dim3 grid(HWP / 128, MT_C, BB);
        hgemm<1><<<grid, 256, SMEM_BYTES>>>(wpp, attn, proj_b, x, x2, CC, CC,
                                            nullptr, nullptr, nullptr);
    }

    // 4) LN2 stats on x2
    ln_stats<<<NPIX / 256, 256>>>(x2, mu2, iv2);

    // 5) fc1 GEMM with fused LN2 + GELU (reads raw x2)
    {
        dim3 grid(HWP / 128, MT_HID, BB);
        hgemm<5><<<grid, 256, SMEM_BYTES>>>(w2p, x2, cb2, nullptr, mlp, HID, CC,
                                            s2, mu2, iv2);
    }

    // 6) fc2 GEMM + bias + residual(x2) -> out
    {
        dim3 grid(HWP / 128, MT_C, BB);
        hgemm<3><<<grid, 256, SMEM_BYTES>>>(w3p, mlp, fc2_b, x2, outp, CC, HID,
                                            nullptr, nullptr, nullptr);
    }
}

// round 9
// speedup vs baseline: 3.7961x; 1.0460x over previous
#include <cuda_runtime.h>
#include <math.h>
#include <stdint.h>

// Problem dims (fixed by the dataset)
#define BB   16
#define CC   392
#define HWP  4096          // 64*64 pixels
#define NH   8
#define HD   49            // head dim
#define HID  1568          // 4*C
#define C3   1176          // 3*C

#define KT   32
#define KC_C    13         // ceil(392/32)
#define KC_HID  49         // 1568/32
#define MT_QKV  10         // ceil(1176/128)
#define MT_C    4          // ceil(392/128)  (proj, fc2 outputs)
#define MT_HID  13         // ceil(1568/128)

// ---------------- scratch (static device, no allocs) ----------------
__device__ float g_qkv [(size_t)BB * C3  * HWP];
__device__ float g_attn[(size_t)BB * CC  * HWP];
__device__ float g_x2  [(size_t)BB * CC  * HWP];
__device__ float g_mlp [(size_t)BB * HID * HWP];
// fragment-permuted weights: [mtile][kchunk][kk(4)][mb(8)][lane(32)][4]
__device__ float g_w1p [(size_t)MT_QKV * KC_C   * 4096];   // qkv  (× ln1_g)
__device__ float g_wpp [(size_t)MT_C   * KC_C   * 4096];   // proj
__device__ float g_w2p [(size_t)MT_HID * KC_C   * 4096];   // fc1  (× ln2_g)
__device__ float g_w3p [(size_t)MT_C   * KC_HID * 4096];   // fc2
__device__ float g_s1  [C3],  g_cb1[C3];
__device__ float g_s2  [HID], g_cb2[HID];
__device__ float g_mu1 [(size_t)BB * HWP], g_iv1[(size_t)BB * HWP];
__device__ float g_mu2 [(size_t)BB * HWP], g_iv2[(size_t)BB * HWP];

// ================= helpers =================
__device__ __forceinline__ uint32_t smem_u32(const void* p) {
    uint32_t a;
    asm("{ .reg .u64 t; cvta.to.shared.u64 t, %1; cvt.u32.u64 %0, t; }"
        : "=r"(a) : "l"(p));
    return a;
}
__device__ __forceinline__ void cp16(uint32_t saddr, const float* g, bool valid) {
    unsigned long long ga;
    asm("cvta.to.global.u64 %0, %1;" : "=l"(ga) : "l"(g));
    int sz = valid ? 16 : 0;
    asm volatile("cp.async.cg.shared.global [%0], [%1], 16, %2;"
                 :: "r"(saddr), "l"(ga), "r"(sz));
}
#define CP_COMMIT() asm volatile("cp.async.commit_group;" ::: "memory")
#define CP_WAIT1()  asm volatile("cp.async.wait_group 1;" ::: "memory")

__device__ __forceinline__ void mma_tf32(float* d, const uint32_t* a, const uint32_t* b) {
    asm volatile(
        "mma.sync.aligned.m16n8k8.row.col.f32.tf32.tf32.f32 "
        "{%0,%1,%2,%3}, {%4,%5,%6,%7}, {%8,%9}, {%0,%1,%2,%3};"
        : "+f"(d[0]), "+f"(d[1]), "+f"(d[2]), "+f"(d[3])
        : "r"(a[0]), "r"(a[1]), "r"(a[2]), "r"(a[3]), "r"(b[0]), "r"(b[1]));
}

// ================= HMMA tf32 GEMM (fragment-permuted A) =================
// D[o, p] = sum_k W[o][k] * X[k][p].  M = 128 out-channels, N = 128 pixels.
// smem per stage: A 16384 B (fragment order) + B [32 k][136 f] 17408 B.
#define STAGES    3
#define B_STRIDE  136
#define STAGE_F   8448            // floats per stage
#define STAGE_B   33792           // bytes per stage
#define SMEM_BYTES (STAGES * STAGE_B)

// MODE: 1 = +bias+res (proj)   3 = +bias+res (fc2)
//       4 = LN-fold (qkv)      5 = LN-fold + exact GELU (fc1)
template<int MODE>
__global__ void __launch_bounds__(256, 2)
hgemm(const float* __restrict__ Wp, const float* __restrict__ X,
      const float* __restrict__ bias, const float* __restrict__ res,
      float* __restrict__ out, int O, int K,
      const float* __restrict__ sarr,
      const float* __restrict__ mu, const float* __restrict__ inv)
{
    extern __shared__ float smf[];
    const uint32_t sb = smem_u32(smf);
    const int tid  = threadIdx.x;
    const int wid  = tid >> 5;
    const int lane = tid & 31;
    const int r = lane >> 2;
    const int c = lane & 3;
    const int warp_m = (wid >> 2) * 64;
    const int warp_n = (wid & 3) * 32;
    const int mb0 = warp_m >> 4;           // 0 or 4

    const int b  = blockIdx.z;
    const int n0 = blockIdx.x * 128;
    const int m0 = blockIdx.y * 128;
    const float* Xb = X + (size_t)b * K * HWP;
    float*       Ob = out + (size_t)b * O * HWP;
    const float* Rb = (MODE == 1 || MODE == 3) ? res + (size_t)b * O * HWP : nullptr;

    const int mvalid = (O - m0 < 128) ? (O - m0) : 128;
    const int rows_w = mvalid - warp_m;        // warp-uniform

    const int NC = (K + KT - 1) / KT;

    auto load_stage = [&](int stage, int ch) {
        uint32_t a_base = sb + stage * STAGE_B;
        uint32_t b_base = a_base + 16384;
        const float* wsrc = Wp + ((size_t)blockIdx.y * NC + ch) * 4096;
        #pragma unroll
        for (int i = 0; i < 4; ++i) {               // A: contiguous 16 KB
            int slot = tid + i * 256;
            cp16(a_base + slot * 16, wsrc + slot * 4, true);
        }
        int k0 = ch * KT;
        #pragma unroll
        for (int i = 0; i < 4; ++i) {               // B: 32 x 128 fl
            int slot = tid + i * 256;
            int kr = slot >> 5, pc = slot & 31;
            int k = k0 + kr;
            bool v = (k < K);
            cp16(b_base + kr * (B_STRIDE * 4) + pc * 16,
                 v ? (Xb + (size_t)k * HWP + n0 + pc * 4) : Xb, v);
        }
    };

    float acc[4][4][4];
    #pragma unroll
    for (int i = 0; i < 4; ++i)
        #pragma unroll
        for (int j = 0; j < 4; ++j)
            #pragma unroll
            for (int t = 0; t < 4; ++t) acc[i][j][t] = 0.f;

    load_stage(0, 0);           CP_COMMIT();
    if (NC > 1) load_stage(1, 1);
    CP_COMMIT();

    for (int ch = 0; ch < NC; ++ch) {
        CP_WAIT1();               // stage ch complete
        __syncthreads();          // all readers of stage ch-1 done

        int ld = ch + 2;
        if (ld < NC) load_stage(ld % STAGES, ld);
        CP_COMMIT();              // exactly one group per iter

        const float* As = smf + (ch % STAGES) * STAGE_F;
        const float* Bs = As + 4096;

        if (rows_w > 0) {
            #pragma unroll
            for (int kkq = 0; kkq < 4; ++kkq) {
                uint32_t af[4][4];
                #pragma unroll
                for (int mt = 0; mt < 4; ++mt) {
                    if (mt * 16 >= rows_w) continue;
                    uint4 v = *reinterpret_cast<const uint4*>(
                        As + kkq * 1024 + (mb0 + mt) * 128 + lane * 4);
                    af[mt][0] = v.x; af[mt][1] = v.y;
                    af[mt][2] = v.z; af[mt][3] = v.w;
                }
                uint32_t bf[4][2];
                #pragma unroll
                for (int nt = 0; nt < 4; ++nt) {
                    int col = warp_n + nt * 8 + r;
                    const float* bp = Bs + (kkq * 8 + c) * B_STRIDE + col;
                    bf[nt][0] = __float_as_uint(bp[0]);
                    bf[nt][1] = __float_as_uint(bp[4 * B_STRIDE]);
                }
                #pragma unroll
                for (int mt = 0; mt < 4; ++mt) {
                    if (mt * 16 >= rows_w) continue;
                    #pragma unroll
                    for (int nt = 0; nt < 4; ++nt)
                        mma_tf32(acc[mt][nt], af[mt], bf[nt]);
                }
            }
        }
    }

    // ---- epilogue ----
    float2 m2[4], i2[4];
    if (MODE >= 4) {
        const float* muB = mu  + (size_t)b * HWP + n0;
        const float* ivB = inv + (size_t)b * HWP + n0;
        #pragma unroll
        for (int nt = 0; nt < 4; ++nt) {
            int p = warp_n + nt * 8 + c * 2;
            m2[nt] = *reinterpret_cast<const float2*>(muB + p);
            i2[nt] = *reinterpret_cast<const float2*>(ivB + p);
        }
    }
    #pragma unroll
    for (int mt = 0; mt < 4; ++mt) {
        #pragma unroll
        for (int half = 0; half < 2; ++half) {
            int o = m0 + warp_m + mt * 16 + half * 8 + r;
            if (o >= O) continue;
            float bv = bias[o];
            float so = (MODE >= 4) ? sarr[o] : 0.f;
            #pragma unroll
            for (int nt = 0; nt < 4; ++nt) {
                int p = n0 + warp_n + nt * 8 + c * 2;
                float v0 = acc[mt][nt][half * 2 + 0];
                float v1 = acc[mt][nt][half * 2 + 1];
                if (MODE == 1 || MODE == 3) {
                    float2 rv = *reinterpret_cast<const float2*>(
                                    Rb + (size_t)o * HWP + p);
                    v0 += bv + rv.x; v1 += bv + rv.y;
                } else {
                    v0 = i2[nt].x * (v0 - m2[nt].x * so) + bv;
                    v1 = i2[nt].y * (v1 - m2[nt].y * so) + bv;
                    if (MODE == 5) {
                        v0 = 0.5f * v0 * (1.0f + erff(v0 * 0.70710678118654752f));
                        v1 = 0.5f * v1 * (1.0f + erff(v1 * 0.70710678118654752f));
                    }
                }
                *reinterpret_cast<float2*>(Ob + (size_t)o * HWP + p)
                    = make_float2(v0, v1);
            }
        }
    }
}

// ---------------- weight permutation into fragment order ----------------
__global__ void __launch_bounds__(256) prep_perm(
    const float* __restrict__ W, const float* __restrict__ g,
    float* __restrict__ Wp, int O, int K, int Mt, int Kc)
{
    size_t gid = (size_t)blockIdx.x * 256 + threadIdx.x;
    size_t total = (size_t)Mt * Kc * 1024;
    if (gid >= total) return;
    int lane = gid & 31;
    int mb   = (gid >> 5) & 7;
    int kk   = (gid >> 8) & 3;
    size_t t = gid >> 10;
    int ch = (int)(t % Kc);
    int mt = (int)(t / Kc);
    int r = lane >> 2, c = lane & 3;
    int row = mt * 128 + mb * 16 + r;
    int col = ch * 32 + kk * 8 + c;
    float v0 = 0.f, v1 = 0.f, v2 = 0.f, v3 = 0.f;
    if (col < K) {
        float gv = g ? g[col] : 1.f;
        if (row     < O) v0 = W[(size_t)row * K + col] * gv;
        if (row + 8 < O) v1 = W[(size_t)(row + 8) * K + col] * gv;
        if (col + 4 < K) {
            float gv4 = g ? g[col + 4] : 1.f;
            if (row     < O) v2 = W[(size_t)row * K + col + 4] * gv4;
            if (row + 8 < O) v3 = W[(size_t)(row + 8) * K + col + 4] * gv4;
        }
    }
    float4* dst = reinterpret_cast<float4*>(Wp + gid * 4);
    *dst = make_float4(v0, v1, v2, v3);
}

// ---------------- LN-fold row constants: s = rowsum(W*g), cb = bias + W@beta --
__global__ void __launch_bounds__(256) prep_scb(
    const float* __restrict__ W, const float* __restrict__ g,
    const float* __restrict__ bta, const float* __restrict__ bias,
    float* __restrict__ sarr, float* __restrict__ cb, int O, int K)
{
    int w = (blockIdx.x * 256 + threadIdx.x) >> 5;
    int lane = threadIdx.x & 31;
    if (w >= O) return;
    float ss = 0.f, bs = 0.f;
    for (int k = lane; k < K; k += 32) {
        float wv = W[(size_t)w * K + k];
        ss += wv * g[k];
        bs += wv * bta[k];
    }
    #pragma unroll
    for (int off = 16; off; off >>= 1) {
        ss += __shfl_xor_sync(0xFFFFFFFFu, ss, off);
        bs += __shfl_xor_sync(0xFFFFFFFFu, bs, off);
    }
    if (lane == 0) { sarr[w] = ss; cb[w] = bias[w] + bs; }
}

// ---------------- LN stats: per-pixel mu, inv ----------------
__global__ void __launch_bounds__(256) ln_stats(
    const float* __restrict__ x, float* __restrict__ mu, float* __restrict__ inv)
{
    int idx = blockIdx.x * blockDim.x + threadIdx.x;
    int b = idx / HWP;
    int p = idx - b * HWP;
    const float* xb = x + (size_t)b * CC * HWP + p;
    float s = 0.f, s2 = 0.f;
    #pragma unroll 8
    for (int c = 0; c < CC; c++) {
        float v = xb[(size_t)c * HWP];
        s += v; s2 += v * v;
    }
    float m  = s * (1.0f / CC);
    float var = s2 * (1.0f / CC) - m * m;
    mu[idx]  = m;
    inv[idx] = rsqrtf(var + 1e-5f);
}

// ---------------- attention + softmax, smem-staged coalesced writes ----------
// One CTA = (b, head, 256-pixel tile). Per-thread softmax over hd=49, results
// staged in smem [tid*49 + d] (stride 49 odd -> bank-conflict-free), then the
// contiguous 256*49-float output region is written with linear float4 stores.
#define ATILE 256
#define ATT_SMEM (ATILE * HD * 4)     // 50176 bytes

__global__ void __launch_bounds__(256) attn_kernel(
    const float* __restrict__ qkv, const float* __restrict__ rel_bias,
    float* __restrict__ out)
{
    extern __shared__ float sm[];
    const int tid = threadIdx.x;
    const int ntile = HWP / ATILE;              // 16
    int tile = blockIdx.x;
    int p0   = (tile & (ntile - 1)) * ATILE;
    int bh   = tile >> 4;
    int head = bh & (NH - 1);
    int b    = bh >> 3;
    int p    = p0 + tid;

    const float* base = qkv + (size_t)b * C3 * HWP;
    const float* qp = base + (size_t)(head * HD) * HWP + p;
    const float* kp = base + (size_t)(CC + head * HD) * HWP + p;
    const float* vp = base + (size_t)(2 * CC + head * HD) * HWP + p;
    const float scale = 0.14285714285714285f;   // 49^-0.5

    float s[HD];
    float mx = -INFINITY;
    #pragma unroll
    for (int d = 0; d < HD; d++) {
        float sv = qp[(size_t)d * HWP] * scale * kp[(size_t)d * HWP]
                   + rel_bias[head * HD + d];
        s[d] = sv;
        mx = fmaxf(mx, sv);
    }
    float sum = 0.f;
    #pragma unroll
    for (int d = 0; d < HD; d++) {
        float e = __expf(s[d] - mx);
        s[d] = e;
        sum += e;
    }
    float inv = 1.0f / sum;
    float* st = sm + tid * HD;
    #pragma unroll
    for (int d = 0; d < HD; d++) {
        st[d] = s[d] * inv * vp[(size_t)d * HWP];
    }
    __syncthreads();

    // contiguous output region for this (b, head, pixel-tile)
    float4* dst = reinterpret_cast<float4*>(
        out + (size_t)b * CC * HWP + (size_t)head * HWP * HD + (size_t)p0 * HD);
    const float4* src = reinterpret_cast<const float4*>(sm);
    #pragma unroll
    for (int i = tid; i < ATILE * HD / 4; i += 256)
        dst[i] = src[i];
}

// ---------------- launch ----------------
extern "C" void kernel_launch(void* const* d_in, const int* in_sizes, int n_in,
                              void* d_out, int out_size)
{
    const float* x      = (const float*)d_in[0];
    const float* ln1_g  = (const float*)d_in[1];
    const float* ln1_b  = (const float*)d_in[2];
    const float* qkv_w  = (const float*)d_in[3];
    const float* qkv_b  = (const float*)d_in[4];
    const float* relb   = (const float*)d_in[5];
    const float* proj_w = (const float*)d_in[6];
    const float* proj_b = (const float*)d_in[7];
    const float* ln2_g  = (const float*)d_in[8];
    const float* ln2_b  = (const float*)d_in[9];
    const float* fc1_w  = (const float*)d_in[10];
    const float* fc1_b  = (const float*)d_in[11];
    const float* fc2_w  = (const float*)d_in[12];
    const float* fc2_b  = (const float*)d_in[13];
    float* outp = (float*)d_out;

    float *qkv, *attn, *x2, *mlp, *w1p, *wpp, *w2p, *w3p;
    float *s1, *cb1, *s2, *cb2, *mu1, *iv1, *mu2, *iv2;
    cudaGetSymbolAddress((void**)&qkv,  g_qkv);
    cudaGetSymbolAddress((void**)&attn, g_attn);
    cudaGetSymbolAddress((void**)&x2,   g_x2);
    cudaGetSymbolAddress((void**)&mlp,  g_mlp);
    cudaGetSymbolAddress((void**)&w1p,  g_w1p);
    cudaGetSymbolAddress((void**)&wpp,  g_wpp);
    cudaGetSymbolAddress((void**)&w2p,  g_w2p);
    cudaGetSymbolAddress((void**)&w3p,  g_w3p);
    cudaGetSymbolAddress((void**)&s1,   g_s1);
    cudaGetSymbolAddress((void**)&cb1,  g_cb1);
    cudaGetSymbolAddress((void**)&s2,   g_s2);
    cudaGetSymbolAddress((void**)&cb2,  g_cb2);
    cudaGetSymbolAddress((void**)&mu1,  g_mu1);
    cudaGetSymbolAddress((void**)&iv1,  g_iv1);
    cudaGetSymbolAddress((void**)&mu2,  g_mu2);
    cudaGetSymbolAddress((void**)&iv2,  g_iv2);

    cudaFuncSetAttribute(hgemm<1>, cudaFuncAttributeMaxDynamicSharedMemorySize, SMEM_BYTES);
    cudaFuncSetAttribute(hgemm<3>, cudaFuncAttributeMaxDynamicSharedMemorySize, SMEM_BYTES);
    cudaFuncSetAttribute(hgemm<4>, cudaFuncAttributeMaxDynamicSharedMemorySize, SMEM_BYTES);
    cudaFuncSetAttribute(hgemm<5>, cudaFuncAttributeMaxDynamicSharedMemorySize, SMEM_BYTES);
    cudaFuncSetAttribute(attn_kernel, cudaFuncAttributeMaxDynamicSharedMemorySize, ATT_SMEM);

    const int NPIX = BB * HWP;

    // 0) weight permutation + LN-fold constants + LN1 stats
    prep_perm<<<(MT_QKV * KC_C * 1024 + 255) / 256, 256>>>(
        qkv_w, ln1_g, w1p, C3, CC, MT_QKV, KC_C);
    prep_perm<<<(MT_C * KC_C * 1024 + 255) / 256, 256>>>(
        proj_w, nullptr, wpp, CC, CC, MT_C, KC_C);
    prep_perm<<<(MT_HID * KC_C * 1024 + 255) / 256, 256>>>(
        fc1_w, ln2_g, w2p, HID, CC, MT_HID, KC_C);
    prep_perm<<<(MT_C * KC_HID * 1024 + 255) / 256, 256>>>(
        fc2_w, nullptr, w3p, CC, HID, MT_C, KC_HID);
    prep_scb<<<(C3 * 32 + 255) / 256, 256>>>(qkv_w, ln1_g, ln1_b, qkv_b,
                                             s1, cb1, C3, CC);
    prep_scb<<<(HID * 32 + 255) / 256, 256>>>(fc1_w, ln2_g, ln2_b, fc1_b,
                                              s2, cb2, HID, CC);
    ln_stats<<<NPIX / 256, 256>>>(x, mu1, iv1);

    // 1) qkv GEMM with fused LN1 (reads raw x)
    {
        dim3 grid(HWP / 128, MT_QKV, BB);
        hgemm<4><<<grid, 256, SMEM_BYTES>>>(w1p, x, cb1, nullptr, qkv, C3, CC,
                                            s1, mu1, iv1);
    }

    // 2) elementwise attention + softmax (scrambled layout, coalesced writes)
    attn_kernel<<<BB * NH * (HWP / ATILE), 256, ATT_SMEM>>>(qkv, relb, attn);

    // 3) proj GEMM + bias + shortcut(x) -> x2
    {
        dim3 grid(HWP / 128, MT_C, BB);
        hgemm<1><<<grid, 256, SMEM_BYTES>>>(wpp, attn, proj_b, x, x2, CC, CC,
                                            nullptr, nullptr, nullptr);
    }

    // 4) LN2 stats on x2
    ln_stats<<<NPIX / 256, 256>>>(x2, mu2, iv2);

    // 5) fc1 GEMM with fused LN2 + GELU (reads raw x2)
    {
        dim3 grid(HWP / 128, MT_HID, BB);
        hgemm<5><<<grid, 256, SMEM_BYTES>>>(w2p, x2, cb2, nullptr, mlp, HID, CC,
                                            s2, mu2, iv2);
    }

    // 6) fc2 GEMM + bias + residual(x2) -> out
    {
        dim3 grid(HWP / 128, MT_C, BB);
        hgemm<3><<<grid, 256, SMEM_BYTES>>>(w3p, mlp, fc2_b, x2, outp, CC, HID,
                                            nullptr, nullptr, nullptr);
    }
}

// round 10
// speedup vs baseline: 3.8626x; 1.0175x over previous
#include <cuda_runtime.h>
#include <math.h>
#include <stdint.h>

// Problem dims (fixed by the dataset)
#define BB   16
#define CC   392
#define HWP  4096          // 64*64 pixels
#define NH   8
#define HD   49            // head dim
#define HID  1568          // 4*C
#define C3   1176          // 3*C

#define KT   32
#define KC_C    13         // ceil(392/32)
#define KC_HID  49         // 1568/32
#define MT_QKV  10         // ceil(1176/128)
#define MT_C    4          // ceil(392/128)
#define MT_HID  13         // ceil(1568/128)

// ---------------- scratch (static device, no allocs) ----------------
__device__ float g_qkv [(size_t)BB * C3  * HWP];
__device__ float g_attn[(size_t)BB * CC  * HWP];
__device__ float g_x2  [(size_t)BB * CC  * HWP];
__device__ float g_mlp [(size_t)BB * HID * HWP];
// fragment-permuted weights: [mtile][kchunk][kk(4)][mb(8)][lane(32)][4]
__device__ float g_w1p [(size_t)MT_QKV * KC_C   * 4096];   // qkv  (× ln1_g)
__device__ float g_wpp [(size_t)MT_C   * KC_C   * 4096];   // proj
__device__ float g_w2p [(size_t)MT_HID * KC_C   * 4096];   // fc1  (× ln2_g)
__device__ float g_w3p [(size_t)MT_C   * KC_HID * 4096];   // fc2
__device__ float g_s1  [C3],  g_cb1[C3];
__device__ float g_s2  [HID], g_cb2[HID];
__device__ float g_mu1 [(size_t)BB * HWP], g_iv1[(size_t)BB * HWP];

// ================= helpers =================
__device__ __forceinline__ uint32_t smem_u32(const void* p) {
    uint32_t a;
    asm("{ .reg .u64 t; cvta.to.shared.u64 t, %1; cvt.u32.u64 %0, t; }"
        : "=r"(a) : "l"(p));
    return a;
}
__device__ __forceinline__ void cp16(uint32_t saddr, const float* g, bool valid) {
    unsigned long long ga;
    asm("cvta.to.global.u64 %0, %1;" : "=l"(ga) : "l"(g));
    int sz = valid ? 16 : 0;
    asm volatile("cp.async.cg.shared.global [%0], [%1], 16, %2;"
                 :: "r"(saddr), "l"(ga), "r"(sz));
}
#define CP_COMMIT() asm volatile("cp.async.commit_group;" ::: "memory")
#define CP_WAIT1()  asm volatile("cp.async.wait_group 1;" ::: "memory")
#define CP_WAIT0()  asm volatile("cp.async.wait_group 0;" ::: "memory")

__device__ __forceinline__ void mma_tf32(float* d, const uint32_t* a, const uint32_t* b) {
    asm volatile(
        "mma.sync.aligned.m16n8k8.row.col.f32.tf32.tf32.f32 "
        "{%0,%1,%2,%3}, {%4,%5,%6,%7}, {%8,%9}, {%0,%1,%2,%3};"
        : "+f"(d[0]), "+f"(d[1]), "+f"(d[2]), "+f"(d[3])
        : "r"(a[0]), "r"(a[1]), "r"(a[2]), "r"(a[3]), "r"(b[0]), "r"(b[1]));
}

// ================= HMMA tf32 GEMM (fragment-permuted A) =================
#define STAGES    3
#define B_STRIDE  136
#define STAGE_F   8448
#define STAGE_B   33792
#define SMEM_BYTES (STAGES * STAGE_B)

// MODE: 1 = +bias+res (proj)   3 = +bias+res (fc2)
//       4 = LN-fold via global mu/iv (qkv)
//       5 = LN-fold via in-CTA stats + exact GELU (fc1; stats fused here)
template<int MODE>
__global__ void __launch_bounds__(256, 2)
hgemm(const float* __restrict__ Wp, const float* __restrict__ X,
      const float* __restrict__ bias, const float* __restrict__ res,
      float* __restrict__ out, int O, int K,
      const float* __restrict__ sarr,
      const float* __restrict__ mu, const float* __restrict__ inv)
{
    extern __shared__ float smf[];
    const uint32_t sb = smem_u32(smf);
    const int tid  = threadIdx.x;
    const int wid  = tid >> 5;
    const int lane = tid & 31;
    const int r = lane >> 2;
    const int c = lane & 3;
    const int warp_m = (wid >> 2) * 64;
    const int warp_n = (wid & 3) * 32;
    const int mb0 = warp_m >> 4;

    const int b  = blockIdx.z;
    const int n0 = blockIdx.x * 128;
    const int m0 = blockIdx.y * 128;
    const float* Xb = X + (size_t)b * K * HWP;
    float*       Ob = out + (size_t)b * O * HWP;
    const float* Rb = (MODE == 1 || MODE == 3) ? res + (size_t)b * O * HWP : nullptr;

    const int mvalid = (O - m0 < 128) ? (O - m0) : 128;
    const int rows_w = mvalid - warp_m;

    const int NC = (K + KT - 1) / KT;

    auto load_stage = [&](int stage, int ch) {
        uint32_t a_base = sb + stage * STAGE_B;
        uint32_t b_base = a_base + 16384;
        const float* wsrc = Wp + ((size_t)blockIdx.y * NC + ch) * 4096;
        #pragma unroll
        for (int i = 0; i < 4; ++i) {
            int slot = tid + i * 256;
            cp16(a_base + slot * 16, wsrc + slot * 4, true);
        }
        int k0 = ch * KT;
        #pragma unroll
        for (int i = 0; i < 4; ++i) {
            int slot = tid + i * 256;
            int kr = slot >> 5, pc = slot & 31;
            int k = k0 + kr;
            bool v = (k < K);
            cp16(b_base + kr * (B_STRIDE * 4) + pc * 16,
                 v ? (Xb + (size_t)k * HWP + n0 + pc * 4) : Xb, v);
        }
    };

    float acc[4][4][4];
    #pragma unroll
    for (int i = 0; i < 4; ++i)
        #pragma unroll
        for (int j = 0; j < 4; ++j)
            #pragma unroll
            for (int t = 0; t < 4; ++t) acc[i][j][t] = 0.f;

    // per-pixel LN stats accumulators (MODE 5 only): this thread's 4 pixels
    float psum[4] = {0.f, 0.f, 0.f, 0.f};
    float psq [4] = {0.f, 0.f, 0.f, 0.f};

    load_stage(0, 0);           CP_COMMIT();
    if (NC > 1) load_stage(1, 1);
    CP_COMMIT();

    for (int ch = 0; ch < NC; ++ch) {
        CP_WAIT1();
        __syncthreads();

        int ld = ch + 2;
        if (ld < NC) load_stage(ld % STAGES, ld);
        CP_COMMIT();

        const float* As = smf + (ch % STAGES) * STAGE_F;
        const float* Bs = As + 4096;

        if (rows_w > 0) {
            #pragma unroll
            for (int kkq = 0; kkq < 4; ++kkq) {
                uint32_t af[4][4];
                #pragma unroll
                for (int mt = 0; mt < 4; ++mt) {
                    if (mt * 16 >= rows_w) continue;
                    uint4 v = *reinterpret_cast<const uint4*>(
                        As + kkq * 1024 + (mb0 + mt) * 128 + lane * 4);
                    af[mt][0] = v.x; af[mt][1] = v.y;
                    af[mt][2] = v.z; af[mt][3] = v.w;
                }
                uint32_t bf[4][2];
                #pragma unroll
                for (int nt = 0; nt < 4; ++nt) {
                    int col = warp_n + nt * 8 + r;
                    const float* bp = Bs + (kkq * 8 + c) * B_STRIDE + col;
                    bf[nt][0] = __float_as_uint(bp[0]);
                    bf[nt][1] = __float_as_uint(bp[4 * B_STRIDE]);
                }
                #pragma unroll
                for (int mt = 0; mt < 4; ++mt) {
                    if (mt * 16 >= rows_w) continue;
                    #pragma unroll
                    for (int nt = 0; nt < 4; ++nt)
                        mma_tf32(acc[mt][nt], af[mt], bf[nt]);
                }
            }
        }

        if (MODE == 5) {
            // accumulate per-pixel sum/sumsq from this stage's B tile.
            // thread owns pixels 4*(tid&31)..+3, k rows (tid>>5)+8i.
            #pragma unroll
            for (int i = 0; i < 4; ++i) {
                int kr = (tid >> 5) + 8 * i;
                float4 v = *reinterpret_cast<const float4*>(
                    Bs + kr * B_STRIDE + (tid & 31) * 4);
                psum[0] += v.x; psq[0] = fmaf(v.x, v.x, psq[0]);
                psum[1] += v.y; psq[1] = fmaf(v.y, v.y, psq[1]);
                psum[2] += v.z; psq[2] = fmaf(v.z, v.z, psq[2]);
                psum[3] += v.w; psq[3] = fmaf(v.w, v.w, psq[3]);
            }
        }
    }

    if (MODE == 5) {
        // cross-warpgroup reduction through reused stage smem
        CP_WAIT0();
        __syncthreads();
        int wg = tid >> 5, pxb = (tid & 31) * 4;
        #pragma unroll
        for (int j = 0; j < 4; ++j) {
            smf[wg * 128 + pxb + j]        = psum[j];
            smf[1024 + wg * 128 + pxb + j] = psq[j];
        }
        __syncthreads();
        if (tid < 128) {
            float s = 0.f, q = 0.f;
            #pragma unroll
            for (int w = 0; w < 8; ++w) {
                s += smf[w * 128 + tid];
                q += smf[1024 + w * 128 + tid];
            }
            float m  = s * (1.0f / CC);
            float iv = rsqrtf(q * (1.0f / CC) - m * m + 1e-5f);
            smf[2048 + tid] = m;
            smf[2176 + tid] = iv;
        }
        __syncthreads();
    }

    // ---- epilogue ----
    float2 m2[4], i2[4];
    if (MODE == 4) {
        const float* muB = mu  + (size_t)b * HWP + n0;
        const float* ivB = inv + (size_t)b * HWP + n0;
        #pragma unroll
        for (int nt = 0; nt < 4; ++nt) {
            int p = warp_n + nt * 8 + c * 2;
            m2[nt] = *reinterpret_cast<const float2*>(muB + p);
            i2[nt] = *reinterpret_cast<const float2*>(ivB + p);
        }
    }
    if (MODE == 5) {
        #pragma unroll
        for (int nt = 0; nt < 4; ++nt) {
            int p = warp_n + nt * 8 + c * 2;
            m2[nt] = *reinterpret_cast<const float2*>(smf + 2048 + p);
            i2[nt] = *reinterpret_cast<const float2*>(smf + 2176 + p);
        }
    }
    #pragma unroll
    for (int mt = 0; mt < 4; ++mt) {
        #pragma unroll
        for (int half = 0; half < 2; ++half) {
            int o = m0 + warp_m + mt * 16 + half * 8 + r;
            if (o >= O) continue;
            float bv = bias[o];
            float so = (MODE >= 4) ? sarr[o] : 0.f;
            #pragma unroll
            for (int nt = 0; nt < 4; ++nt) {
                int p = n0 + warp_n + nt * 8 + c * 2;
                float v0 = acc[mt][nt][half * 2 + 0];
                float v1 = acc[mt][nt][half * 2 + 1];
                if (MODE == 1 || MODE == 3) {
                    float2 rv = *reinterpret_cast<const float2*>(
                                    Rb + (size_t)o * HWP + p);
                    v0 += bv + rv.x; v1 += bv + rv.y;
                } else {
                    v0 = i2[nt].x * (v0 - m2[nt].x * so) + bv;
                    v1 = i2[nt].y * (v1 - m2[nt].y * so) + bv;
                    if (MODE == 5) {
                        v0 = 0.5f * v0 * (1.0f + erff(v0 * 0.70710678118654752f));
                        v1 = 0.5f * v1 * (1.0f + erff(v1 * 0.70710678118654752f));
                    }
                }
                *reinterpret_cast<float2*>(Ob + (size_t)o * HWP + p)
                    = make_float2(v0, v1);
            }
        }
    }
}

// ================= mega-prep: all independent pre-GEMM work in ONE launch ====
// CTA ranges: perm1 | perm2 | perm3 | perm4 | scb1 | scb2 | ln1-stats
#define P1_CTAS  (MT_QKV * KC_C * 4)     // 520   (1024 threads per (mt,ch) group)
#define P2_CTAS  (MT_C   * KC_C * 4)     // 208
#define P3_CTAS  (MT_HID * KC_C * 4)     // 676
#define P4_CTAS  (MT_C   * KC_HID * 4)   // 784
#define SCB1_CTAS ((C3  * 32 + 255) / 256)   // 147
#define SCB2_CTAS ((HID * 32 + 255) / 256)   // 196
#define STAT_CTAS (BB * HWP / 256)           // 256
#define PREP_CTAS (P1_CTAS + P2_CTAS + P3_CTAS + P4_CTAS + SCB1_CTAS + SCB2_CTAS + STAT_CTAS)

struct PrepArgs {
    const float *qkv_w, *proj_w, *fc1_w, *fc2_w;
    const float *ln1_g, *ln1_b, *ln2_g, *ln2_b;
    const float *qkv_b, *fc1_b;
    const float *x;
    float *w1p, *wpp, *w2p, *w3p;
    float *s1, *cb1, *s2, *cb2;
    float *mu1, *iv1;
};

__device__ __forceinline__ void do_perm(
    const float* __restrict__ W, const float* __restrict__ g,
    float* __restrict__ Wp, int O, int K, int Kc, size_t gid)
{
    int lane = gid & 31;
    int mb   = (gid >> 5) & 7;
    int kk   = (gid >> 8) & 3;
    size_t t = gid >> 10;
    int ch = (int)(t % Kc);
    int mt = (int)(t / Kc);
    int r = lane >> 2, c = lane & 3;
    int row = mt * 128 + mb * 16 + r;
    int col = ch * 32 + kk * 8 + c;
    float v0 = 0.f, v1 = 0.f, v2 = 0.f, v3 = 0.f;
    if (col < K) {
        float gv = g ? g[col] : 1.f;
        if (row     < O) v0 = W[(size_t)row * K + col] * gv;
        if (row + 8 < O) v1 = W[(size_t)(row + 8) * K + col] * gv;
        if (col + 4 < K) {
            float gv4 = g ? g[col + 4] : 1.f;
            if (row     < O) v2 = W[(size_t)row * K + col + 4] * gv4;
            if (row + 8 < O) v3 = W[(size_t)(row + 8) * K + col + 4] * gv4;
        }
    }
    *reinterpret_cast<float4*>(Wp + gid * 4) = make_float4(v0, v1, v2, v3);
}

__device__ __forceinline__ void do_scb(
    const float* __restrict__ W, const float* __restrict__ g,
    const float* __restrict__ bta, const float* __restrict__ bias,
    float* __restrict__ sarr, float* __restrict__ cb, int O, int K,
    int idx, int lane)
{
    int w = idx >> 5;
    if (w >= O) return;
    float ss = 0.f, bs = 0.f;
    for (int k = lane; k < K; k += 32) {
        float wv = W[(size_t)w * K + k];
        ss += wv * g[k];
        bs += wv * bta[k];
    }
    #pragma unroll
    for (int off = 16; off; off >>= 1) {
        ss += __shfl_xor_sync(0xFFFFFFFFu, ss, off);
        bs += __shfl_xor_sync(0xFFFFFFFFu, bs, off);
    }
    if (lane == 0) { sarr[w] = ss; cb[w] = bias[w] + bs; }
}

__global__ void __launch_bounds__(256) mega_prep(PrepArgs a)
{
    int cta = blockIdx.x;
    int tid = threadIdx.x;
    if (cta < P1_CTAS) {
        do_perm(a.qkv_w, a.ln1_g, a.w1p, C3, CC, KC_C,
                (size_t)cta * 256 + tid);
        return;
    }
    cta -= P1_CTAS;
    if (cta < P2_CTAS) {
        do_perm(a.proj_w, nullptr, a.wpp, CC, CC, KC_C,
                (size_t)cta * 256 + tid);
        return;
    }
    cta -= P2_CTAS;
    if (cta < P3_CTAS) {
        do_perm(a.fc1_w, a.ln2_g, a.w2p, HID, CC, KC_C,
                (size_t)cta * 256 + tid);
        return;
    }
    cta -= P3_CTAS;
    if (cta < P4_CTAS) {
        do_perm(a.fc2_w, nullptr, a.w3p, CC, HID, KC_HID,
                (size_t)cta * 256 + tid);
        return;
    }
    cta -= P4_CTAS;
    if (cta < SCB1_CTAS) {
        do_scb(a.qkv_w, a.ln1_g, a.ln1_b, a.qkv_b, a.s1, a.cb1, C3, CC,
               cta * 256 + tid, tid & 31);
        return;
    }
    cta -= SCB1_CTAS;
    if (cta < SCB2_CTAS) {
        do_scb(a.fc1_w, a.ln2_g, a.ln2_b, a.fc1_b, a.s2, a.cb2, HID, CC,
               cta * 256 + tid, tid & 31);
        return;
    }
    cta -= SCB2_CTAS;
    {   // LN1 stats
        int idx = cta * 256 + tid;
        int b = idx / HWP;
        int p = idx - b * HWP;
        const float* xb = a.x + (size_t)b * CC * HWP + p;
        float s = 0.f, s2 = 0.f;
        #pragma unroll 8
        for (int c = 0; c < CC; c++) {
            float v = xb[(size_t)c * HWP];
            s += v; s2 += v * v;
        }
        float m  = s * (1.0f / CC);
        float var = s2 * (1.0f / CC) - m * m;
        a.mu1[idx] = m;
        a.iv1[idx] = rsqrtf(var + 1e-5f);
    }
}

// ---------------- attention + softmax, smem-staged coalesced writes ----------
#define ATILE 256
#define ATT_SMEM (ATILE * HD * 4)     // 50176 bytes

__global__ void __launch_bounds__(256) attn_kernel(
    const float* __restrict__ qkv, const float* __restrict__ rel_bias,
    float* __restrict__ out)
{
    extern __shared__ float sm[];
    const int tid = threadIdx.x;
    const int ntile = HWP / ATILE;              // 16
    int tile = blockIdx.x;
    int p0   = (tile & (ntile - 1)) * ATILE;
    int bh   = tile >> 4;
    int head = bh & (NH - 1);
    int b    = bh >> 3;
    int p    = p0 + tid;

    const float* base = qkv + (size_t)b * C3 * HWP;
    const float* qp = base + (size_t)(head * HD) * HWP + p;
    const float* kp = base + (size_t)(CC + head * HD) * HWP + p;
    const float* vp = base + (size_t)(2 * CC + head * HD) * HWP + p;
    const float scale = 0.14285714285714285f;   // 49^-0.5

    float s[HD];
    float mx = -INFINITY;
    #pragma unroll
    for (int d = 0; d < HD; d++) {
        float sv = qp[(size_t)d * HWP] * scale * kp[(size_t)d * HWP]
                   + rel_bias[head * HD + d];
        s[d] = sv;
        mx = fmaxf(mx, sv);
    }
    float sum = 0.f;
    #pragma unroll
    for (int d = 0; d < HD; d++) {
        float e = __expf(s[d] - mx);
        s[d] = e;
        sum += e;
    }
    float inv = 1.0f / sum;
    float* st = sm + tid * HD;
    #pragma unroll
    for (int d = 0; d < HD; d++) {
        st[d] = s[d] * inv * vp[(size_t)d * HWP];
    }
    __syncthreads();

    float4* dst = reinterpret_cast<float4*>(
        out + (size_t)b * CC * HWP + (size_t)head * HWP * HD + (size_t)p0 * HD);
    const float4* src = reinterpret_cast<const float4*>(sm);
    #pragma unroll
    for (int i = tid; i < ATILE * HD / 4; i += 256)
        dst[i] = src[i];
}

// ---------------- launch ----------------
extern "C" void kernel_launch(void* const* d_in, const int* in_sizes, int n_in,
                              void* d_out, int out_size)
{
    const float* x      = (const float*)d_in[0];
    const float* ln1_g  = (const float*)d_in[1];
    const float* ln1_b  = (const float*)d_in[2];
    const float* qkv_w  = (const float*)d_in[3];
    const float* qkv_b  = (const float*)d_in[4];
    const float* relb   = (const float*)d_in[5];
    const float* proj_w = (const float*)d_in[6];
    const float* proj_b = (const float*)d_in[7];
    const float* ln2_g  = (const float*)d_in[8];
    const float* ln2_b  = (const float*)d_in[9];
    const float* fc1_w  = (const float*)d_in[10];
    const float* fc1_b  = (const float*)d_in[11];
    const float* fc2_w  = (const float*)d_in[12];
    const float* fc2_b  = (const float*)d_in[13];
    float* outp = (float*)d_out;

    float *qkv, *attn, *x2, *mlp, *w1p, *wpp, *w2p, *w3p;
    float *s1, *cb1, *s2, *cb2, *mu1, *iv1;
    cudaGetSymbolAddress((void**)&qkv,  g_qkv);
    cudaGetSymbolAddress((void**)&attn, g_attn);
    cudaGetSymbolAddress((void**)&x2,   g_x2);
    cudaGetSymbolAddress((void**)&mlp,  g_mlp);
    cudaGetSymbolAddress((void**)&w1p,  g_w1p);
    cudaGetSymbolAddress((void**)&wpp,  g_wpp);
    cudaGetSymbolAddress((void**)&w2p,  g_w2p);
    cudaGetSymbolAddress((void**)&w3p,  g_w3p);
    cudaGetSymbolAddress((void**)&s1,   g_s1);
    cudaGetSymbolAddress((void**)&cb1,  g_cb1);
    cudaGetSymbolAddress((void**)&s2,   g_s2);
    cudaGetSymbolAddress((void**)&cb2,  g_cb2);
    cudaGetSymbolAddress((void**)&mu1,  g_mu1);
    cudaGetSymbolAddress((void**)&iv1,  g_iv1);

    cudaFuncSetAttribute(hgemm<1>, cudaFuncAttributeMaxDynamicSharedMemorySize, SMEM_BYTES);
    cudaFuncSetAttribute(hgemm<3>, cudaFuncAttributeMaxDynamicSharedMemorySize, SMEM_BYTES);
    cudaFuncSetAttribute(hgemm<4>, cudaFuncAttributeMaxDynamicSharedMemorySize, SMEM_BYTES);
    cudaFuncSetAttribute(hgemm<5>, cudaFuncAttributeMaxDynamicSharedMemorySize, SMEM_BYTES);
    cudaFuncSetAttribute(attn_kernel, cudaFuncAttributeMaxDynamicSharedMemorySize, ATT_SMEM);

    // 0) ONE prep launch: 4 weight perms + 2 LN-fold consts + LN1 stats
    {
        PrepArgs a;
        a.qkv_w = qkv_w; a.proj_w = proj_w; a.fc1_w = fc1_w; a.fc2_w = fc2_w;
        a.ln1_g = ln1_g; a.ln1_b = ln1_b; a.ln2_g = ln2_g; a.ln2_b = ln2_b;
        a.qkv_b = qkv_b; a.fc1_b = fc1_b; a.x = x;
        a.w1p = w1p; a.wpp = wpp; a.w2p = w2p; a.w3p = w3p;
        a.s1 = s1; a.cb1 = cb1; a.s2 = s2; a.cb2 = cb2;
        a.mu1 = mu1; a.iv1 = iv1;
        mega_prep<<<PREP_CTAS, 256>>>(a);
    }

    // 1) qkv GEMM with fused LN1
    {
        dim3 grid(HWP / 128, MT_QKV, BB);
        hgemm<4><<<grid, 256, SMEM_BYTES>>>(w1p, x, cb1, nullptr, qkv, C3, CC,
                                            s1, mu1, iv1);
    }

    // 2) elementwise attention + softmax (scrambled layout, coalesced writes)
    attn_kernel<<<BB * NH * (HWP / ATILE), 256, ATT_SMEM>>>(qkv, relb, attn);

    // 3) proj GEMM + bias + shortcut(x) -> x2
    {
        dim3 grid(HWP / 128, MT_C, BB);
        hgemm<1><<<grid, 256, SMEM_BYTES>>>(wpp, attn, proj_b, x, x2, CC, CC,
                                            nullptr, nullptr, nullptr);
    }

    // 4) fc1 GEMM with in-CTA LN2 stats + fold + GELU (reads raw x2)
    {
        dim3 grid(HWP / 128, MT_HID, BB);
        hgemm<5><<<grid, 256, SMEM_BYTES>>>(w2p, x2, cb2, nullptr, mlp, HID, CC,
                                            s2, nullptr, nullptr);
    }

    // 5) fc2 GEMM + bias + residual(x2) -> out
    {
        dim3 grid(HWP / 128, MT_C, BB);
        hgemm<3><<<grid, 256, SMEM_BYTES>>>(w3p, mlp, fc2_b, x2, outp, CC, HID,
                                            nullptr, nullptr, nullptr);
    }
}

// round 11
// speedup vs baseline: 6.1969x; 1.6043x over previous
#include <cuda_runtime.h>
#include <cuda_fp16.h>
#include <math.h>
#include <stdint.h>

// Problem dims (fixed by the dataset)
#define BB   16
#define CC   392
#define HWP  4096          // 64*64 pixels
#define NH   8
#define HD   49            // head dim
#define HID  1568          // 4*C
#define C3   1176          // 3*C

#define KT   32
#define KC_C    13
#define KC_HID  49
#define MT_QKV  10
#define MT_C    4
#define MT_HID  13

// ---------------- scratch (static device, no allocs) ----------------
__device__ __half g_xh  [(size_t)BB * CC  * HWP];   // fp16 copy of x
__device__ __half g_qkv [(size_t)BB * C3  * HWP];
__device__ __half g_attn[(size_t)BB * CC  * HWP];
__device__ float  g_x2  [(size_t)BB * CC  * HWP];   // fp32 (residual source)
__device__ __half g_x2h [(size_t)BB * CC  * HWP];
__device__ __half g_mlp [(size_t)BB * HID * HWP];
// fragment-permuted fp16 weights: [mtile][kchunk][kstep2][mb8][lane32] x uint4
__device__ uint4 g_w1p [(size_t)MT_QKV * KC_C   * 512];
__device__ uint4 g_wpp [(size_t)MT_C   * KC_C   * 512];
__device__ uint4 g_w2p [(size_t)MT_HID * KC_C   * 512];
__device__ uint4 g_w3p [(size_t)MT_C   * KC_HID * 512];
__device__ float g_s1  [C3],  g_cb1[C3];
__device__ float g_s2  [HID], g_cb2[HID];
__device__ float g_mu1 [(size_t)BB * HWP], g_iv1[(size_t)BB * HWP];

// ================= helpers =================
__device__ __forceinline__ uint32_t smem_u32(const void* p) {
    uint32_t a;
    asm("{ .reg .u64 t; cvta.to.shared.u64 t, %1; cvt.u32.u64 %0, t; }"
        : "=r"(a) : "l"(p));
    return a;
}
__device__ __forceinline__ void cp16(uint32_t saddr, const void* g, bool valid) {
    unsigned long long ga;
    asm("cvta.to.global.u64 %0, %1;" : "=l"(ga) : "l"(g));
    int sz = valid ? 16 : 0;
    asm volatile("cp.async.cg.shared.global [%0], [%1], 16, %2;"
                 :: "r"(saddr), "l"(ga), "r"(sz));
}
#define CP_COMMIT() asm volatile("cp.async.commit_group;" ::: "memory")
#define CP_WAIT1()  asm volatile("cp.async.wait_group 1;" ::: "memory")
#define CP_WAIT0()  asm volatile("cp.async.wait_group 0;" ::: "memory")

__device__ __forceinline__ uint32_t pack2(float a, float b) {
    __half2 h = __floats2half2_rn(a, b);
    return *reinterpret_cast<uint32_t*>(&h);
}
__device__ __forceinline__ void mma_f16(float* d, const uint32_t* a, const uint32_t* b) {
    asm volatile(
        "mma.sync.aligned.m16n8k16.row.col.f32.f16.f16.f32 "
        "{%0,%1,%2,%3}, {%4,%5,%6,%7}, {%8,%9}, {%0,%1,%2,%3};"
        : "+f"(d[0]), "+f"(d[1]), "+f"(d[2]), "+f"(d[3])
        : "r"(a[0]), "r"(a[1]), "r"(a[2]), "r"(a[3]), "r"(b[0]), "r"(b[1]));
}
__device__ __forceinline__ void ldmx4t(uint32_t& r0, uint32_t& r1,
                                       uint32_t& r2, uint32_t& r3, uint32_t addr) {
    asm volatile("ldmatrix.sync.aligned.m8n8.x4.trans.shared.b16 {%0,%1,%2,%3}, [%4];"
        : "=r"(r0), "=r"(r1), "=r"(r2), "=r"(r3) : "r"(addr));
}

// ================= fp16 HMMA GEMM (fragment-permuted A, ldmatrix B) ==========
// D[o, p] = sum_k W[o][k] * X[k][p].  M=128 o, N=128 p, K-chunk 32 (2 k16 steps)
// stage: A 8192 B (fragment order) + B 32 rows x 272 B = 8704 B -> 16896 B
#define STAGES    3
#define B_PITCH   272              // bytes per k-row (128 px * 2B + 16B pad)
#define B_PITCH_H 136              // halves
#define STAGE_B   16896
#define SMEM_BYTES (STAGES * STAGE_B)

// MODE: 1 = +bias+res, out fp32 + fp16 (proj -> x2, x2h)
//       3 = +bias+res, out fp32 (fc2 -> final)
//       4 = LN-fold via global mu/iv, out fp16 (qkv)
//       5 = LN-fold via in-CTA stats + GELU, out fp16 (fc1)
template<int MODE>
__global__ void __launch_bounds__(256, 2)
hgemm(const uint4* __restrict__ Wp, const __half* __restrict__ X,
      const float* __restrict__ bias, const float* __restrict__ res,
      float* __restrict__ out, __half* __restrict__ outh, int O, int K,
      const float* __restrict__ sarr,
      const float* __restrict__ mu, const float* __restrict__ inv)
{
    extern __shared__ float smf[];
    char* smc = reinterpret_cast<char*>(smf);
    const uint32_t sb = smem_u32(smf);
    const int tid  = threadIdx.x;
    const int wid  = tid >> 5;
    const int lane = tid & 31;
    const int r = lane >> 2;
    const int c = lane & 3;
    const int warp_m = (wid >> 2) * 64;
    const int warp_n = (wid & 3) * 32;
    const int mb0 = warp_m >> 4;

    const int b  = blockIdx.z;
    const int n0 = blockIdx.x * 128;
    const int m0 = blockIdx.y * 128;
    const __half* Xb = X + (size_t)b * K * HWP;
    float*  Ob  = out  ? out  + (size_t)b * O * HWP : nullptr;
    __half* Obh = outh ? outh + (size_t)b * O * HWP : nullptr;
    const float* Rb = (MODE == 1 || MODE == 3) ? res + (size_t)b * O * HWP : nullptr;

    const int mvalid = (O - m0 < 128) ? (O - m0) : 128;
    const int rows_w = mvalid - warp_m;

    const int NC = (K + KT - 1) / KT;

    auto load_stage = [&](int stage, int ch) {
        uint32_t a_base = sb + stage * STAGE_B;
        uint32_t b_base = a_base + 8192;
        const uint4* wsrc = Wp + ((size_t)blockIdx.y * NC + ch) * 512;
        #pragma unroll
        for (int i = 0; i < 2; ++i) {               // A: 512 x 16B
            int slot = tid + i * 256;
            cp16(a_base + slot * 16, wsrc + slot, true);
        }
        int k0 = ch * KT;
        #pragma unroll
        for (int i = 0; i < 2; ++i) {               // B: 32 rows x 16 x 16B
            int slot = tid + i * 256;
            int kr = slot >> 4, pc = slot & 15;
            int k = k0 + kr;
            bool v = (k < K);
            cp16(b_base + kr * B_PITCH + pc * 16,
                 v ? (const void*)(Xb + (size_t)k * HWP + n0 + pc * 8) : (const void*)Xb, v);
        }
    };

    float acc[4][4][4];
    #pragma unroll
    for (int i = 0; i < 4; ++i)
        #pragma unroll
        for (int j = 0; j < 4; ++j)
            #pragma unroll
            for (int t = 0; t < 4; ++t) acc[i][j][t] = 0.f;

    float psum[4] = {0.f, 0.f, 0.f, 0.f};
    float psq [4] = {0.f, 0.f, 0.f, 0.f};

    load_stage(0, 0);           CP_COMMIT();
    if (NC > 1) load_stage(1, 1);
    CP_COMMIT();

    for (int ch = 0; ch < NC; ++ch) {
        CP_WAIT1();
        __syncthreads();

        int ld = ch + 2;
        if (ld < NC) load_stage(ld % STAGES, ld);
        CP_COMMIT();

        const uint32_t stoff = (uint32_t)((ch % STAGES) * STAGE_B);

        if (rows_w > 0) {
            #pragma unroll
            for (int ks = 0; ks < 2; ++ks) {
                uint32_t af[4][4];
                #pragma unroll
                for (int mt = 0; mt < 4; ++mt) {
                    if (mt * 16 >= rows_w) continue;
                    uint4 v = *reinterpret_cast<const uint4*>(
                        smc + stoff + (ks * 256 + (mb0 + mt) * 32 + lane) * 16);
                    af[mt][0] = v.x; af[mt][1] = v.y;
                    af[mt][2] = v.z; af[mt][3] = v.w;
                }
                uint32_t bf[8];
                int rl = ks * 16 + (lane & 15);
                uint32_t baddr = sb + stoff + 8192 + rl * B_PITCH
                               + (warp_n + ((lane >> 4) << 3)) * 2;
                ldmx4t(bf[0], bf[1], bf[2], bf[3], baddr);
                ldmx4t(bf[4], bf[5], bf[6], bf[7], baddr + 32);
                #pragma unroll
                for (int mt = 0; mt < 4; ++mt) {
                    if (mt * 16 >= rows_w) continue;
                    #pragma unroll
                    for (int nt = 0; nt < 4; ++nt)
                        mma_f16(acc[mt][nt], af[mt], bf + nt * 2);
                }
            }
        }

        if (MODE == 5) {
            const __half* Bsh = reinterpret_cast<const __half*>(smc + stoff + 8192);
            #pragma unroll
            for (int i = 0; i < 4; ++i) {
                int kr = (tid >> 5) + 8 * i;
                const __half2* hp = reinterpret_cast<const __half2*>(
                    Bsh + kr * B_PITCH_H + (tid & 31) * 4);
                float2 f0 = __half22float2(hp[0]);
                float2 f1 = __half22float2(hp[1]);
                psum[0] += f0.x; psq[0] = fmaf(f0.x, f0.x, psq[0]);
                psum[1] += f0.y; psq[1] = fmaf(f0.y, f0.y, psq[1]);
                psum[2] += f1.x; psq[2] = fmaf(f1.x, f1.x, psq[2]);
                psum[3] += f1.y; psq[3] = fmaf(f1.y, f1.y, psq[3]);
            }
        }
    }

    if (MODE == 5) {
        CP_WAIT0();
        __syncthreads();
        int wg = tid >> 5, pxb = (tid & 31) * 4;
        #pragma unroll
        for (int j = 0; j < 4; ++j) {
            smf[wg * 128 + pxb + j]        = psum[j];
            smf[1024 + wg * 128 + pxb + j] = psq[j];
        }
        __syncthreads();
        if (tid < 128) {
            float s = 0.f, q = 0.f;
            #pragma unroll
            for (int w = 0; w < 8; ++w) {
                s += smf[w * 128 + tid];
                q += smf[1024 + w * 128 + tid];
            }
            float m  = s * (1.0f / CC);
            float iv = rsqrtf(q * (1.0f / CC) - m * m + 1e-5f);
            smf[2048 + tid] = m;
            smf[2176 + tid] = iv;
        }
        __syncthreads();
    }

    // ---- epilogue ----
    float2 m2[4], i2[4];
    if (MODE == 4) {
        const float* muB = mu  + (size_t)b * HWP + n0;
        const float* ivB = inv + (size_t)b * HWP + n0;
        #pragma unroll
        for (int nt = 0; nt < 4; ++nt) {
            int p = warp_n + nt * 8 + c * 2;
            m2[nt] = *reinterpret_cast<const float2*>(muB + p);
            i2[nt] = *reinterpret_cast<const float2*>(ivB + p);
        }
    }
    if (MODE == 5) {
        #pragma unroll
        for (int nt = 0; nt < 4; ++nt) {
            int p = warp_n + nt * 8 + c * 2;
            m2[nt] = *reinterpret_cast<const float2*>(smf + 2048 + p);
            i2[nt] = *reinterpret_cast<const float2*>(smf + 2176 + p);
        }
    }
    #pragma unroll
    for (int mt = 0; mt < 4; ++mt) {
        #pragma unroll
        for (int half = 0; half < 2; ++half) {
            int o = m0 + warp_m + mt * 16 + half * 8 + r;
            if (o >= O) continue;
            float bv = bias[o];
            float so = (MODE >= 4) ? sarr[o] : 0.f;
            #pragma unroll
            for (int nt = 0; nt < 4; ++nt) {
                int p = n0 + warp_n + nt * 8 + c * 2;
                float v0 = acc[mt][nt][half * 2 + 0];
                float v1 = acc[mt][nt][half * 2 + 1];
                if (MODE == 1 || MODE == 3) {
                    float2 rv = *reinterpret_cast<const float2*>(
                                    Rb + (size_t)o * HWP + p);
                    v0 += bv + rv.x; v1 += bv + rv.y;
                } else {
                    v0 = i2[nt].x * (v0 - m2[nt].x * so) + bv;
                    v1 = i2[nt].y * (v1 - m2[nt].y * so) + bv;
                    if (MODE == 5) {
                        v0 = 0.5f * v0 * (1.0f + erff(v0 * 0.70710678118654752f));
                        v1 = 0.5f * v1 * (1.0f + erff(v1 * 0.70710678118654752f));
                    }
                }
                if (MODE == 1 || MODE == 3)
                    *reinterpret_cast<float2*>(Ob + (size_t)o * HWP + p)
                        = make_float2(v0, v1);
                if (MODE == 1 || MODE == 4 || MODE == 5)
                    *reinterpret_cast<__half2*>(Obh + (size_t)o * HWP + p)
                        = __floats2half2_rn(v0, v1);
            }
        }
    }
}

// ================= mega-prep (one launch) ====================================
// ranges: xh-convert | perm1 | perm2 | perm3 | perm4 | scb1 | scb2 | ln1-stats
#define XH_CTAS  (BB * CC * HWP / (256 * 8))     // 12544
#define P1_CTAS  (MT_QKV * KC_C * 2)             // 260
#define P2_CTAS  (MT_C   * KC_C * 2)             // 104
#define P3_CTAS  (MT_HID * KC_C * 2)             // 338
#define P4_CTAS  (MT_C   * KC_HID * 2)           // 392
#define SCB1_CTAS ((C3  * 32 + 255) / 256)
#define SCB2_CTAS ((HID * 32 + 255) / 256)
#define STAT_CTAS (BB * HWP / 256)
#define PREP_CTAS (XH_CTAS + P1_CTAS + P2_CTAS + P3_CTAS + P4_CTAS + \
                   SCB1_CTAS + SCB2_CTAS + STAT_CTAS)

struct PrepArgs {
    const float *qkv_w, *proj_w, *fc1_w, *fc2_w;
    const float *ln1_g, *ln1_b, *ln2_g, *ln2_b;
    const float *qkv_b, *fc1_b;
    const float *x;
    __half *xh;
    uint4 *w1p, *wpp, *w2p, *w3p;
    float *s1, *cb1, *s2, *cb2;
    float *mu1, *iv1;
};

__device__ __forceinline__ void do_perm_h(
    const float* __restrict__ W, const float* __restrict__ g,
    uint4* __restrict__ Wp, int O, int K, int Kc, size_t gid)
{
    int lane = (int)(gid & 31);
    int mb   = (int)((gid >> 5) & 7);
    int ks   = (int)((gid >> 8) & 1);
    size_t t = gid >> 9;
    int ch = (int)(t % Kc);
    int mt = (int)(t / Kc);
    int r = lane >> 2, c = lane & 3;
    int row0 = mt * 128 + mb * 16 + r, row1 = row0 + 8;
    int k0 = ch * 32 + ks * 16 + 2 * c;
    float w00=0.f,w01=0.f,w02=0.f,w03=0.f,w10=0.f,w11=0.f,w12=0.f,w13=0.f;
    auto ld = [&](int rr, int kk) -> float {
        return (kk < K) ? W[(size_t)rr * K + kk] * (g ? g[kk] : 1.f) : 0.f;
    };
    if (row0 < O) { w00=ld(row0,k0); w01=ld(row0,k0+1); w02=ld(row0,k0+8); w03=ld(row0,k0+9); }
    if (row1 < O) { w10=ld(row1,k0); w11=ld(row1,k0+1); w12=ld(row1,k0+8); w13=ld(row1,k0+9); }
    uint4 o;
    o.x = pack2(w00, w01); o.y = pack2(w10, w11);
    o.z = pack2(w02, w03); o.w = pack2(w12, w13);
    Wp[gid] = o;
}

__device__ __forceinline__ void do_scb(
    const float* __restrict__ W, const float* __restrict__ g,
    const float* __restrict__ bta, const float* __restrict__ bias,
    float* __restrict__ sarr, float* __restrict__ cb, int O, int K,
    int idx, int lane)
{
    int w = idx >> 5;
    if (w >= O) return;
    float ss = 0.f, bs = 0.f;
    for (int k = lane; k < K; k += 32) {
        float wv = W[(size_t)w * K + k];
        ss += wv * g[k];
        bs += wv * bta[k];
    }
    #pragma unroll
    for (int off = 16; off; off >>= 1) {
        ss += __shfl_xor_sync(0xFFFFFFFFu, ss, off);
        bs += __shfl_xor_sync(0xFFFFFFFFu, bs, off);
    }
    if (lane == 0) { sarr[w] = ss; cb[w] = bias[w] + bs; }
}

__global__ void __launch_bounds__(256) mega_prep(PrepArgs a)
{
    int cta = blockIdx.x;
    int tid = threadIdx.x;
    if (cta < XH_CTAS) {   // x -> fp16
        size_t i0 = ((size_t)cta * 256 + tid) * 8;
        float4 f0 = *reinterpret_cast<const float4*>(a.x + i0);
        float4 f1 = *reinterpret_cast<const float4*>(a.x + i0 + 4);
        uint4 o;
        o.x = pack2(f0.x, f0.y); o.y = pack2(f0.z, f0.w);
        o.z = pack2(f1.x, f1.y); o.w = pack2(f1.z, f1.w);
        *reinterpret_cast<uint4*>(a.xh + i0) = o;
        return;
    }
    cta -= XH_CTAS;
    if (cta < P1_CTAS) { do_perm_h(a.qkv_w, a.ln1_g, a.w1p, C3, CC, KC_C, (size_t)cta*256+tid); return; }
    cta -= P1_CTAS;
    if (cta < P2_CTAS) { do_perm_h(a.proj_w, nullptr, a.wpp, CC, CC, KC_C, (size_t)cta*256+tid); return; }
    cta -= P2_CTAS;
    if (cta < P3_CTAS) { do_perm_h(a.fc1_w, a.ln2_g, a.w2p, HID, CC, KC_C, (size_t)cta*256+tid); return; }
    cta -= P3_CTAS;
    if (cta < P4_CTAS) { do_perm_h(a.fc2_w, nullptr, a.w3p, CC, HID, KC_HID, (size_t)cta*256+tid); return; }
    cta -= P4_CTAS;
    if (cta < SCB1_CTAS) { do_scb(a.qkv_w, a.ln1_g, a.ln1_b, a.qkv_b, a.s1, a.cb1, C3, CC, cta*256+tid, tid&31); return; }
    cta -= SCB1_CTAS;
    if (cta < SCB2_CTAS) { do_scb(a.fc1_w, a.ln2_g, a.ln2_b, a.fc1_b, a.s2, a.cb2, HID, CC, cta*256+tid, tid&31); return; }
    cta -= SCB2_CTAS;
    {   // LN1 stats (fp32 x)
        int idx = cta * 256 + tid;
        int b = idx / HWP;
        int p = idx - b * HWP;
        const float* xb = a.x + (size_t)b * CC * HWP + p;
        float s = 0.f, s2 = 0.f;
        #pragma unroll 8
        for (int c = 0; c < CC; c++) {
            float v = xb[(size_t)c * HWP];
            s += v; s2 += v * v;
        }
        float m  = s * (1.0f / CC);
        float var = s2 * (1.0f / CC) - m * m;
        a.mu1[idx] = m;
        a.iv1[idx] = rsqrtf(var + 1e-5f);
    }
}

// ---------------- attention + softmax (fp16 in/out, smem-staged writes) ------
#define ATILE 256
#define ATT_SMEM (ATILE * HD * 2)     // 25088 bytes

__global__ void __launch_bounds__(256) attn_kernel(
    const __half* __restrict__ qkv, const float* __restrict__ rel_bias,
    __half* __restrict__ out)
{
    extern __shared__ __half smh[];
    const int tid = threadIdx.x;
    int tile = blockIdx.x;
    int p0   = (tile & 15) * ATILE;
    int bh   = tile >> 4;
    int head = bh & (NH - 1);
    int b    = bh >> 3;
    int p    = p0 + tid;

    const __half* base = qkv + (size_t)b * C3 * HWP;
    const __half* qp = base + (size_t)(head * HD) * HWP + p;
    const __half* kp = base + (size_t)(CC + head * HD) * HWP + p;
    const __half* vp = base + (size_t)(2 * CC + head * HD) * HWP + p;
    const float scale = 0.14285714285714285f;   // 49^-0.5

    float s[HD];
    float mx = -INFINITY;
    #pragma unroll
    for (int d = 0; d < HD; d++) {
        float sv = __half2float(qp[(size_t)d * HWP]) * scale
                 * __half2float(kp[(size_t)d * HWP]) + rel_bias[head * HD + d];
        s[d] = sv;
        mx = fmaxf(mx, sv);
    }
    float sum = 0.f;
    #pragma unroll
    for (int d = 0; d < HD; d++) {
        float e = __expf(s[d] - mx);
        s[d] = e;
        sum += e;
    }
    float inv = 1.0f / sum;
    __half* st = smh + tid * HD;
    #pragma unroll
    for (int d = 0; d < HD; d++) {
        st[d] = __float2half_rn(s[d] * inv * __half2float(vp[(size_t)d * HWP]));
    }
    __syncthreads();

    uint4* dst = reinterpret_cast<uint4*>(
        out + (size_t)b * CC * HWP + (size_t)head * HWP * HD + (size_t)p0 * HD);
    const uint4* src = reinterpret_cast<const uint4*>(smh);
    #pragma unroll
    for (int i = tid; i < ATILE * HD / 8; i += 256)
        dst[i] = src[i];
}

// ---------------- launch ----------------
extern "C" void kernel_launch(void* const* d_in, const int* in_sizes, int n_in,
                              void* d_out, int out_size)
{
    const float* x      = (const float*)d_in[0];
    const float* ln1_g  = (const float*)d_in[1];
    const float* ln1_b  = (const float*)d_in[2];
    const float* qkv_w  = (const float*)d_in[3];
    const float* qkv_b  = (const float*)d_in[4];
    const float* relb   = (const float*)d_in[5];
    const float* proj_w = (const float*)d_in[6];
    const float* proj_b = (const float*)d_in[7];
    const float* ln2_g  = (const float*)d_in[8];
    const float* ln2_b  = (const float*)d_in[9];
    const float* fc1_w  = (const float*)d_in[10];
    const float* fc1_b  = (const float*)d_in[11];
    const float* fc2_w  = (const float*)d_in[12];
    const float* fc2_b  = (const float*)d_in[13];
    float* outp = (float*)d_out;

    __half *xh, *qkv, *attn, *x2h, *mlp;
    float *x2;
    uint4 *w1p, *wpp, *w2p, *w3p;
    float *s1, *cb1, *s2, *cb2, *mu1, *iv1;
    cudaGetSymbolAddress((void**)&xh,   g_xh);
    cudaGetSymbolAddress((void**)&qkv,  g_qkv);
    cudaGetSymbolAddress((void**)&attn, g_attn);
    cudaGetSymbolAddress((void**)&x2,   g_x2);
    cudaGetSymbolAddress((void**)&x2h,  g_x2h);
    cudaGetSymbolAddress((void**)&mlp,  g_mlp);
    cudaGetSymbolAddress((void**)&w1p,  g_w1p);
    cudaGetSymbolAddress((void**)&wpp,  g_wpp);
    cudaGetSymbolAddress((void**)&w2p,  g_w2p);
    cudaGetSymbolAddress((void**)&w3p,  g_w3p);
    cudaGetSymbolAddress((void**)&s1,   g_s1);
    cudaGetSymbolAddress((void**)&cb1,  g_cb1);
    cudaGetSymbolAddress((void**)&s2,   g_s2);
    cudaGetSymbolAddress((void**)&cb2,  g_cb2);
    cudaGetSymbolAddress((void**)&mu1,  g_mu1);
    cudaGetSymbolAddress((void**)&iv1,  g_iv1);

    cudaFuncSetAttribute(hgemm<1>, cudaFuncAttributeMaxDynamicSharedMemorySize, SMEM_BYTES);
    cudaFuncSetAttribute(hgemm<3>, cudaFuncAttributeMaxDynamicSharedMemorySize, SMEM_BYTES);
    cudaFuncSetAttribute(hgemm<4>, cudaFuncAttributeMaxDynamicSharedMemorySize, SMEM_BYTES);
    cudaFuncSetAttribute(hgemm<5>, cudaFuncAttributeMaxDynamicSharedMemorySize, SMEM_BYTES);

    // 0) ONE prep launch: x->fp16 + 4 fp16 weight perms + LN consts + LN1 stats
    {
        PrepArgs a;
        a.qkv_w = qkv_w; a.proj_w = proj_w; a.fc1_w = fc1_w; a.fc2_w = fc2_w;
        a.ln1_g = ln1_g; a.ln1_b = ln1_b; a.ln2_g = ln2_g; a.ln2_b = ln2_b;
        a.qkv_b = qkv_b; a.fc1_b = fc1_b; a.x = x; a.xh = xh;
        a.w1p = w1p; a.wpp = wpp; a.w2p = w2p; a.w3p = w3p;
        a.s1 = s1; a.cb1 = cb1; a.s2 = s2; a.cb2 = cb2;
        a.mu1 = mu1; a.iv1 = iv1;
        mega_prep<<<PREP_CTAS, 256>>>(a);
    }

    // 1) qkv GEMM with fused LN1 (B = xh) -> qkv fp16
    {
        dim3 grid(HWP / 128, MT_QKV, BB);
        hgemm<4><<<grid, 256, SMEM_BYTES>>>(w1p, xh, cb1, nullptr,
                                            nullptr, qkv, C3, CC, s1, mu1, iv1);
    }

    // 2) attention + softmax (fp16)
    attn_kernel<<<BB * NH * (HWP / ATILE), 256, ATT_SMEM>>>(qkv, relb, attn);

    // 3) proj GEMM + bias + shortcut(x) -> x2 fp32 + x2h fp16
    {
        dim3 grid(HWP / 128, MT_C, BB);
        hgemm<1><<<grid, 256, SMEM_BYTES>>>(wpp, attn, proj_b, x,
                                            x2, x2h, CC, CC, nullptr, nullptr, nullptr);
    }

    // 4) fc1 GEMM with in-CTA LN2 stats + fold + GELU (B = x2h) -> mlp fp16
    {
        dim3 grid(HWP / 128, MT_HID, BB);
        hgemm<5><<<grid, 256, SMEM_BYTES>>>(w2p, x2h, cb2, nullptr,
                                            nullptr, mlp, HID, CC, s2, nullptr, nullptr);
    }

    // 5) fc2 GEMM + bias + residual(x2) -> out fp32
    {
        dim3 grid(HWP / 128, MT_C, BB);
        hgemm<3><<<grid, 256, SMEM_BYTES>>>(w3p, mlp, fc2_b, x2,
                                            outp, nullptr, CC, HID, nullptr, nullptr, nullptr);
    }
}